// round 1
// baseline (speedup 1.0000x reference)
#include <cuda_runtime.h>
#include <math.h>

// Problem constants
#define D_MODEL 1024
#define NHEADS  16
#define HD      64
#define BATCH   4
#define SEQ     2048
#define MTOK    (BATCH * SEQ)   // 8192 rows

// Scratch (device globals: allocation inside kernel_launch is forbidden)
__device__ float g_qkv[(size_t)MTOK * 3 * D_MODEL];  // [8192, 3072]
__device__ float g_y  [(size_t)MTOK * D_MODEL];      // [8192, 1024]

// ---------------------------------------------------------------------------
// SGEMM: C[M,N] = A[M,K] @ B[K,N], row-major, M%128==0, N%128==0, K%8==0
// 128x128 block tile, BK=8, 256 threads, 8x8 per-thread microtile
// (split-fragment layout: rows {ty*4, 64+ty*4}, cols {tx*4, 64+tx*4})
// ---------------------------------------------------------------------------
__global__ __launch_bounds__(256)
void sgemm_kernel(const float* __restrict__ A, const float* __restrict__ Bm,
                  float* __restrict__ C, int M, int N, int K)
{
    __shared__ float As[8][128];   // transposed A tile: As[k][m]
    __shared__ float Bs[8][128];   // Bs[k][n]

    const int tid = threadIdx.x;
    const int bn = blockIdx.x, bm = blockIdx.y;
    const int tx = tid & 15, ty = tid >> 4;

    // loader indices
    const int arow = tid >> 1;          // 0..127
    const int acol = (tid & 1) * 4;     // 0 or 4
    const int brow = tid >> 5;          // 0..7
    const int bcol = (tid & 31) * 4;    // 0..124

    const float* Ap = A + (size_t)(bm * 128 + arow) * K + acol;
    const float* Bp = Bm + (size_t)brow * N + bn * 128 + bcol;

    float acc[8][8];
#pragma unroll
    for (int i = 0; i < 8; i++)
#pragma unroll
        for (int j = 0; j < 8; j++) acc[i][j] = 0.0f;

    for (int k0 = 0; k0 < K; k0 += 8) {
        float4 a4 = *(const float4*)(Ap + k0);
        float4 b4 = *(const float4*)(Bp + (size_t)k0 * N);

        As[acol + 0][arow] = a4.x;
        As[acol + 1][arow] = a4.y;
        As[acol + 2][arow] = a4.z;
        As[acol + 3][arow] = a4.w;
        *(float4*)&Bs[brow][bcol] = b4;
        __syncthreads();

#pragma unroll
        for (int k = 0; k < 8; k++) {
            float4 a0 = *(const float4*)&As[k][ty * 4];
            float4 a1 = *(const float4*)&As[k][64 + ty * 4];
            float4 b0 = *(const float4*)&Bs[k][tx * 4];
            float4 b1 = *(const float4*)&Bs[k][64 + tx * 4];
            float av[8] = {a0.x, a0.y, a0.z, a0.w, a1.x, a1.y, a1.z, a1.w};
            float bv[8] = {b0.x, b0.y, b0.z, b0.w, b1.x, b1.y, b1.z, b1.w};
#pragma unroll
            for (int i = 0; i < 8; i++)
#pragma unroll
                for (int j = 0; j < 8; j++)
                    acc[i][j] = fmaf(av[i], bv[j], acc[i][j]);
        }
        __syncthreads();
    }

    const int col0 = bn * 128 + tx * 4;
#pragma unroll
    for (int i = 0; i < 8; i++) {
        int r = bm * 128 + ((i < 4) ? (ty * 4 + i) : (64 + ty * 4 + (i - 4)));
        float4 v0 = make_float4(acc[i][0], acc[i][1], acc[i][2], acc[i][3]);
        float4 v1 = make_float4(acc[i][4], acc[i][5], acc[i][6], acc[i][7]);
        *(float4*)&C[(size_t)r * N + col0]      = v0;
        *(float4*)&C[(size_t)r * N + col0 + 64] = v1;
    }
}

// ---------------------------------------------------------------------------
// Flash attention (causal, online softmax), fp32.
// One block = one (b, h, 64-query tile). 256 threads as 16x16; each thread
// owns a 4(row)x4(col) fragment of the 64x64 score tile and of the 64x64
// (rows x headdim) output tile.
// qkv layout (from projection): row r = b*SEQ+s, within row:
//   q at h*64, k at 1024 + h*64, v at 2048 + h*64
// ---------------------------------------------------------------------------
#define QS_STRIDE 65
__global__ __launch_bounds__(256)
void flash_attn_kernel()
{
    extern __shared__ float sm[];
    float (*Qs)[QS_STRIDE] = (float(*)[QS_STRIDE])sm;                   // 64x65
    float (*Ks)[QS_STRIDE] = (float(*)[QS_STRIDE])(sm + 64 * QS_STRIDE);// 64x65 (reused for P)
    float (*Vs)[64]        = (float(*)[64])(sm + 2 * 64 * QS_STRIDE);   // 64x64 (float4-aligned)

    const int tid = threadIdx.x;
    const int tx = tid & 15, ty = tid >> 4;
    const int b = blockIdx.z, h = blockIdx.y, qt = blockIdx.x;
    const int q0 = qt * 64;

    // loader indices: each thread loads 4 rows (r = ch*16 + lr), 4 cols at lc
    const int lr = tid >> 4;
    const int lc = (tid & 15) * 4;

    // ---- load Q tile (scaled by 1/sqrt(64)) ----
#pragma unroll
    for (int ch = 0; ch < 4; ch++) {
        int r = ch * 16 + lr;
        const float* src = g_qkv + (size_t)(b * SEQ + q0 + r) * (3 * D_MODEL) + h * HD + lc;
        float4 v = *(const float4*)src;
        Qs[r][lc + 0] = v.x * 0.125f;
        Qs[r][lc + 1] = v.y * 0.125f;
        Qs[r][lc + 2] = v.z * 0.125f;
        Qs[r][lc + 3] = v.w * 0.125f;
    }

    float m[4], l[4], acc[4][4];
#pragma unroll
    for (int i = 0; i < 4; i++) {
        m[i] = -1e30f; l[i] = 0.0f;
#pragma unroll
        for (int j = 0; j < 4; j++) acc[i][j] = 0.0f;
    }

    for (int j = 0; j <= qt; j++) {
        const int k0 = j * 64;
        // ---- load K and V tiles ----
#pragma unroll
        for (int ch = 0; ch < 4; ch++) {
            int r = ch * 16 + lr;
            const float* ksrc = g_qkv + (size_t)(b * SEQ + k0 + r) * (3 * D_MODEL) + D_MODEL + h * HD + lc;
            const float* vsrc = g_qkv + (size_t)(b * SEQ + k0 + r) * (3 * D_MODEL) + 2 * D_MODEL + h * HD + lc;
            float4 kv = *(const float4*)ksrc;
            Ks[r][lc + 0] = kv.x; Ks[r][lc + 1] = kv.y;
            Ks[r][lc + 2] = kv.z; Ks[r][lc + 3] = kv.w;
            *(float4*)&Vs[r][lc] = *(const float4*)vsrc;
        }
        __syncthreads();

        // ---- S = Q @ K^T (per-thread 4x4 fragment) ----
        float s[4][4];
#pragma unroll
        for (int i = 0; i < 4; i++)
#pragma unroll
            for (int jj = 0; jj < 4; jj++) s[i][jj] = 0.0f;

#pragma unroll 8
        for (int k = 0; k < 64; k++) {
            float qr[4], kc[4];
#pragma unroll
            for (int i = 0; i < 4; i++) qr[i] = Qs[ty * 4 + i][k];
#pragma unroll
            for (int jj = 0; jj < 4; jj++) kc[jj] = Ks[tx * 4 + jj][k];
#pragma unroll
            for (int i = 0; i < 4; i++)
#pragma unroll
                for (int jj = 0; jj < 4; jj++)
                    s[i][jj] = fmaf(qr[i], kc[jj], s[i][jj]);
        }

        // ---- causal mask on diagonal tile ----
        if (j == qt) {
#pragma unroll
            for (int i = 0; i < 4; i++)
#pragma unroll
                for (int jj = 0; jj < 4; jj++)
                    if (tx * 4 + jj > ty * 4 + i) s[i][jj] = -1e30f;
        }

        // ---- online softmax (row stats reduced across the 16 tx lanes) ----
#pragma unroll
        for (int i = 0; i < 4; i++) {
            float tm = fmaxf(fmaxf(s[i][0], s[i][1]), fmaxf(s[i][2], s[i][3]));
#pragma unroll
            for (int o = 1; o < 16; o <<= 1)
                tm = fmaxf(tm, __shfl_xor_sync(0xffffffffu, tm, o));
            float mnew = fmaxf(m[i], tm);
            float sum = 0.0f;
#pragma unroll
            for (int jj = 0; jj < 4; jj++) {
                s[i][jj] = __expf(s[i][jj] - mnew);
                sum += s[i][jj];
            }
#pragma unroll
            for (int o = 1; o < 16; o <<= 1)
                sum += __shfl_xor_sync(0xffffffffu, sum, o);
            float alpha = __expf(m[i] - mnew);
            l[i] = l[i] * alpha + sum;
            m[i] = mnew;
#pragma unroll
            for (int jj = 0; jj < 4; jj++) acc[i][jj] *= alpha;
        }

        __syncthreads();  // everyone done reading Ks before overwrite with P
#pragma unroll
        for (int i = 0; i < 4; i++)
#pragma unroll
            for (int jj = 0; jj < 4; jj++)
                Ks[ty * 4 + i][tx * 4 + jj] = s[i][jj];
        __syncthreads();

        // ---- O += P @ V ----
#pragma unroll 8
        for (int t = 0; t < 64; t++) {
            float pr[4];
#pragma unroll
            for (int i = 0; i < 4; i++) pr[i] = Ks[ty * 4 + i][t];
            float4 v4 = *(const float4*)&Vs[t][tx * 4];
#pragma unroll
            for (int i = 0; i < 4; i++) {
                acc[i][0] = fmaf(pr[i], v4.x, acc[i][0]);
                acc[i][1] = fmaf(pr[i], v4.y, acc[i][1]);
                acc[i][2] = fmaf(pr[i], v4.z, acc[i][2]);
                acc[i][3] = fmaf(pr[i], v4.w, acc[i][3]);
            }
        }
        __syncthreads();  // before next tile overwrites Ks/Vs
    }

    // ---- epilogue: normalize and write y[b,s,h,hd] ----
#pragma unroll
    for (int i = 0; i < 4; i++) {
        float inv = 1.0f / l[i];
        int r = q0 + ty * 4 + i;
        float4 o = make_float4(acc[i][0] * inv, acc[i][1] * inv,
                               acc[i][2] * inv, acc[i][3] * inv);
        *(float4*)&g_y[(size_t)(b * SEQ + r) * D_MODEL + h * HD + tx * 4] = o;
    }
}

// ---------------------------------------------------------------------------
extern "C" void kernel_launch(void* const* d_in, const int* in_sizes, int n_in,
                              void* d_out, int out_size)
{
    const float* x      = (const float*)d_in[0];   // [4,2048,1024]
    const float* w_qkv  = (const float*)d_in[1];   // [1024,3072]
    const float* w_proj = (const float*)d_in[2];   // [1024,1024]
    float* out = (float*)d_out;                    // [4,2048,1024]

    float *qkv_ptr, *y_ptr;
    cudaGetSymbolAddress((void**)&qkv_ptr, g_qkv);
    cudaGetSymbolAddress((void**)&y_ptr, g_y);

    const int smem_flash = (2 * 64 * QS_STRIDE + 64 * 64) * (int)sizeof(float); // 49664
    cudaFuncSetAttribute(flash_attn_kernel,
                         cudaFuncAttributeMaxDynamicSharedMemorySize, smem_flash);

    // 1) qkv = x @ w_qkv   [8192,1024] @ [1024,3072]
    sgemm_kernel<<<dim3(3 * D_MODEL / 128, MTOK / 128), 256>>>(
        x, w_qkv, qkv_ptr, MTOK, 3 * D_MODEL, D_MODEL);

    // 2) flash attention -> g_y [8192,1024]
    flash_attn_kernel<<<dim3(SEQ / 64, NHEADS, BATCH), 256, smem_flash>>>();

    // 3) out = y @ w_proj  [8192,1024] @ [1024,1024]
    sgemm_kernel<<<dim3(D_MODEL / 128, MTOK / 128), 256>>>(
        y_ptr, w_proj, out, MTOK, D_MODEL, D_MODEL);
}

// round 3
// speedup vs baseline: 1.5481x; 1.5481x over previous
#include <cuda_runtime.h>
#include <math.h>
#include <stdint.h>

// Problem constants
#define D_MODEL 1024
#define NHEADS  16
#define HD      64
#define BATCH   4
#define SEQ     2048
#define MTOK    (BATCH * SEQ)   // 8192 rows

// Scratch (device globals: allocation inside kernel_launch is forbidden)
__device__ float g_qkv[(size_t)MTOK * 3 * D_MODEL];  // [8192, 3072]
__device__ float g_y  [(size_t)MTOK * D_MODEL];      // [8192, 1024]

// ---------------------------------------------------------------------------
// tf32 round-to-nearest (unbiased; avoids HMMA truncation bias)
// ---------------------------------------------------------------------------
__device__ __forceinline__ float tf32r(float x) {
    uint32_t o;
    asm("cvt.rna.tf32.f32 %0, %1;" : "=r"(o) : "f"(x));
    return __uint_as_float(o);
}

// ---------------------------------------------------------------------------
// TF32 mma.sync GEMM: C[M,N] = A[M,K] @ B[K,N], row-major.
// 128x128 CTA tile, BK=16, 256 threads = 8 warps (2x4), warp tile 64x32.
// Double-buffered smem, register-staged global loads overlap compute.
// A fragments from As[m][20] (conflict-free), B from Bs[k][136] (conflict-free).
// ---------------------------------------------------------------------------
#define BK 16
#define AS_STRIDE 20
#define BS_STRIDE 136

__global__ __launch_bounds__(256, 2)
void gemm_tf32_mma(const float* __restrict__ A, const float* __restrict__ B,
                   float* __restrict__ C, int M, int N, int K)
{
    __shared__ __align__(16) float As[2][128][AS_STRIDE];
    __shared__ __align__(16) float Bs[2][BK][BS_STRIDE];

    const int tid = threadIdx.x;
    const int wid = tid >> 5, lane = tid & 31;
    const int wm = wid >> 2, wn = wid & 3;     // warp grid 2(M) x 4(N)
    const int gId = lane >> 2, tig = lane & 3; // mma quad layout
    const int bm = blockIdx.y, bn = blockIdx.x;

    const float* Ab = A + (size_t)(bm * 128) * K;
    const float* Bb = B + bn * 128;

    float acc[4][4][4];
#pragma unroll
    for (int i = 0; i < 4; i++)
#pragma unroll
        for (int j = 0; j < 4; j++)
#pragma unroll
            for (int r = 0; r < 4; r++) acc[i][j][r] = 0.0f;

    float4 av[2], bv[2];

    // global -> regs for K-chunk kt
    auto ldg = [&](int kt) {
#pragma unroll
        for (int i = 0; i < 2; i++) {
            int idx = tid + 256 * i;
            av[i] = *(const float4*)(Ab + (size_t)(idx >> 2) * K + kt * BK + (idx & 3) * 4);
            bv[i] = *(const float4*)(Bb + (size_t)(kt * BK + (idx >> 5)) * N + (idx & 31) * 4);
        }
    };
    // regs -> smem stage s (with tf32 rounding)
    auto sts = [&](int s) {
#pragma unroll
        for (int i = 0; i < 2; i++) {
            int idx = tid + 256 * i;
            int r = idx >> 2, kc = (idx & 3) * 4;
            As[s][r][kc + 0] = tf32r(av[i].x);
            As[s][r][kc + 1] = tf32r(av[i].y);
            As[s][r][kc + 2] = tf32r(av[i].z);
            As[s][r][kc + 3] = tf32r(av[i].w);
            int kr = idx >> 5, nc = (idx & 31) * 4;
            float4 b4 = make_float4(tf32r(bv[i].x), tf32r(bv[i].y),
                                    tf32r(bv[i].z), tf32r(bv[i].w));
            *(float4*)&Bs[s][kr][nc] = b4;
        }
    };
    // compute from stage s (2 ksteps of 8)
    auto compute = [&](int s) {
#pragma unroll
        for (int ks = 0; ks < 2; ks++) {
            const int kb = ks * 8;
            uint32_t a[4][4], b[4][2];
#pragma unroll
            for (int mf = 0; mf < 4; mf++) {
                int m0 = wm * 64 + mf * 16 + gId;
                a[mf][0] = __float_as_uint(As[s][m0][kb + tig]);
                a[mf][1] = __float_as_uint(As[s][m0 + 8][kb + tig]);
                a[mf][2] = __float_as_uint(As[s][m0][kb + tig + 4]);
                a[mf][3] = __float_as_uint(As[s][m0 + 8][kb + tig + 4]);
            }
#pragma unroll
            for (int nf = 0; nf < 4; nf++) {
                int n0 = wn * 32 + nf * 8 + gId;
                b[nf][0] = __float_as_uint(Bs[s][kb + tig][n0]);
                b[nf][1] = __float_as_uint(Bs[s][kb + tig + 4][n0]);
            }
#pragma unroll
            for (int mf = 0; mf < 4; mf++)
#pragma unroll
                for (int nf = 0; nf < 4; nf++)
                    asm volatile(
                        "mma.sync.aligned.m16n8k8.row.col.f32.tf32.tf32.f32 "
                        "{%0,%1,%2,%3}, {%4,%5,%6,%7}, {%8,%9}, {%0,%1,%2,%3};"
                        : "+f"(acc[mf][nf][0]), "+f"(acc[mf][nf][1]),
                          "+f"(acc[mf][nf][2]), "+f"(acc[mf][nf][3])
                        : "r"(a[mf][0]), "r"(a[mf][1]), "r"(a[mf][2]), "r"(a[mf][3]),
                          "r"(b[nf][0]), "r"(b[nf][1]));
        }
    };

    const int nkt = K / BK;
    ldg(0);
    sts(0);
    __syncthreads();
    for (int kt = 0; kt < nkt; kt++) {
        const int cur = kt & 1;
        const bool more = (kt + 1 < nkt);
        if (more) ldg(kt + 1);
        compute(cur);
        if (more) sts(cur ^ 1);
        __syncthreads();
    }

    // epilogue: accumulators -> C
#pragma unroll
    for (int mf = 0; mf < 4; mf++) {
        int r0 = bm * 128 + wm * 64 + mf * 16 + gId;
#pragma unroll
        for (int nf = 0; nf < 4; nf++) {
            int c0 = bn * 128 + wn * 32 + nf * 8 + 2 * tig;
            *(float2*)&C[(size_t)r0 * N + c0] =
                make_float2(acc[mf][nf][0], acc[mf][nf][1]);
            *(float2*)&C[(size_t)(r0 + 8) * N + c0] =
                make_float2(acc[mf][nf][2], acc[mf][nf][3]);
        }
    }
}

// ---------------------------------------------------------------------------
// Flash attention (causal, online softmax), fp32 — unchanged (known good).
// ---------------------------------------------------------------------------
#define QS_STRIDE 65
__global__ __launch_bounds__(256)
void flash_attn_kernel()
{
    extern __shared__ float sm[];
    float (*Qs)[QS_STRIDE] = (float(*)[QS_STRIDE])sm;                    // 64x65
    float (*Ks)[QS_STRIDE] = (float(*)[QS_STRIDE])(sm + 64 * QS_STRIDE); // 64x65 (reused for P)
    float (*Vs)[64]        = (float(*)[64])(sm + 2 * 64 * QS_STRIDE);    // 64x64

    const int tid = threadIdx.x;
    const int tx = tid & 15, ty = tid >> 4;
    const int b = blockIdx.z, h = blockIdx.y, qt = blockIdx.x;
    const int q0 = qt * 64;

    const int lr = tid >> 4;
    const int lc = (tid & 15) * 4;

#pragma unroll
    for (int ch = 0; ch < 4; ch++) {
        int r = ch * 16 + lr;
        const float* src = g_qkv + (size_t)(b * SEQ + q0 + r) * (3 * D_MODEL) + h * HD + lc;
        float4 v = *(const float4*)src;
        Qs[r][lc + 0] = v.x * 0.125f;
        Qs[r][lc + 1] = v.y * 0.125f;
        Qs[r][lc + 2] = v.z * 0.125f;
        Qs[r][lc + 3] = v.w * 0.125f;
    }

    float m[4], l[4], acc[4][4];
#pragma unroll
    for (int i = 0; i < 4; i++) {
        m[i] = -1e30f; l[i] = 0.0f;
#pragma unroll
        for (int j = 0; j < 4; j++) acc[i][j] = 0.0f;
    }

    for (int j = 0; j <= qt; j++) {
        const int k0 = j * 64;
#pragma unroll
        for (int ch = 0; ch < 4; ch++) {
            int r = ch * 16 + lr;
            const float* ksrc = g_qkv + (size_t)(b * SEQ + k0 + r) * (3 * D_MODEL) + D_MODEL + h * HD + lc;
            const float* vsrc = g_qkv + (size_t)(b * SEQ + k0 + r) * (3 * D_MODEL) + 2 * D_MODEL + h * HD + lc;
            float4 kv = *(const float4*)ksrc;
            Ks[r][lc + 0] = kv.x; Ks[r][lc + 1] = kv.y;
            Ks[r][lc + 2] = kv.z; Ks[r][lc + 3] = kv.w;
            *(float4*)&Vs[r][lc] = *(const float4*)vsrc;
        }
        __syncthreads();

        float s[4][4];
#pragma unroll
        for (int i = 0; i < 4; i++)
#pragma unroll
            for (int jj = 0; jj < 4; jj++) s[i][jj] = 0.0f;

#pragma unroll 8
        for (int k = 0; k < 64; k++) {
            float qr[4], kc[4];
#pragma unroll
            for (int i = 0; i < 4; i++) qr[i] = Qs[ty * 4 + i][k];
#pragma unroll
            for (int jj = 0; jj < 4; jj++) kc[jj] = Ks[tx * 4 + jj][k];
#pragma unroll
            for (int i = 0; i < 4; i++)
#pragma unroll
                for (int jj = 0; jj < 4; jj++)
                    s[i][jj] = fmaf(qr[i], kc[jj], s[i][jj]);
        }

        if (j == qt) {
#pragma unroll
            for (int i = 0; i < 4; i++)
#pragma unroll
                for (int jj = 0; jj < 4; jj++)
                    if (tx * 4 + jj > ty * 4 + i) s[i][jj] = -1e30f;
        }

#pragma unroll
        for (int i = 0; i < 4; i++) {
            float tm = fmaxf(fmaxf(s[i][0], s[i][1]), fmaxf(s[i][2], s[i][3]));
#pragma unroll
            for (int o = 1; o < 16; o <<= 1)
                tm = fmaxf(tm, __shfl_xor_sync(0xffffffffu, tm, o));
            float mnew = fmaxf(m[i], tm);
            float sum = 0.0f;
#pragma unroll
            for (int jj = 0; jj < 4; jj++) {
                s[i][jj] = __expf(s[i][jj] - mnew);
                sum += s[i][jj];
            }
#pragma unroll
            for (int o = 1; o < 16; o <<= 1)
                sum += __shfl_xor_sync(0xffffffffu, sum, o);
            float alpha = __expf(m[i] - mnew);
            l[i] = l[i] * alpha + sum;
            m[i] = mnew;
#pragma unroll
            for (int jj = 0; jj < 4; jj++) acc[i][jj] *= alpha;
        }

        __syncthreads();
#pragma unroll
        for (int i = 0; i < 4; i++)
#pragma unroll
            for (int jj = 0; jj < 4; jj++)
                Ks[ty * 4 + i][tx * 4 + jj] = s[i][jj];
        __syncthreads();

#pragma unroll 8
        for (int t = 0; t < 64; t++) {
            float pr[4];
#pragma unroll
            for (int i = 0; i < 4; i++) pr[i] = Ks[ty * 4 + i][t];
            float4 v4 = *(const float4*)&Vs[t][tx * 4];
#pragma unroll
            for (int i = 0; i < 4; i++) {
                acc[i][0] = fmaf(pr[i], v4.x, acc[i][0]);
                acc[i][1] = fmaf(pr[i], v4.y, acc[i][1]);
                acc[i][2] = fmaf(pr[i], v4.z, acc[i][2]);
                acc[i][3] = fmaf(pr[i], v4.w, acc[i][3]);
            }
        }
        __syncthreads();
    }

#pragma unroll
    for (int i = 0; i < 4; i++) {
        float inv = 1.0f / l[i];
        int r = q0 + ty * 4 + i;
        float4 o = make_float4(acc[i][0] * inv, acc[i][1] * inv,
                               acc[i][2] * inv, acc[i][3] * inv);
        *(float4*)&g_y[(size_t)(b * SEQ + r) * D_MODEL + h * HD + tx * 4] = o;
    }
}

// ---------------------------------------------------------------------------
extern "C" void kernel_launch(void* const* d_in, const int* in_sizes, int n_in,
                              void* d_out, int out_size)
{
    const float* x      = (const float*)d_in[0];   // [4,2048,1024]
    const float* w_qkv  = (const float*)d_in[1];   // [1024,3072]
    const float* w_proj = (const float*)d_in[2];   // [1024,1024]
    float* out = (float*)d_out;                    // [4,2048,1024]

    float *qkv_ptr, *y_ptr;
    cudaGetSymbolAddress((void**)&qkv_ptr, g_qkv);
    cudaGetSymbolAddress((void**)&y_ptr, g_y);

    const int smem_flash = (2 * 64 * QS_STRIDE + 64 * 64) * (int)sizeof(float); // 49664
    cudaFuncSetAttribute(flash_attn_kernel,
                         cudaFuncAttributeMaxDynamicSharedMemorySize, smem_flash);

    // 1) qkv = x @ w_qkv   [8192,1024] @ [1024,3072]  (tf32 mma.sync)
    gemm_tf32_mma<<<dim3(3 * D_MODEL / 128, MTOK / 128), 256>>>(
        x, w_qkv, qkv_ptr, MTOK, 3 * D_MODEL, D_MODEL);

    // 2) flash attention -> g_y [8192,1024]
    flash_attn_kernel<<<dim3(SEQ / 64, NHEADS, BATCH), 256, smem_flash>>>();

    // 3) out = y @ w_proj  [8192,1024] @ [1024,1024]  (tf32 mma.sync)
    gemm_tf32_mma<<<dim3(D_MODEL / 128, MTOK / 128), 256>>>(
        y_ptr, w_proj, out, MTOK, D_MODEL, D_MODEL);
}

// round 4
// speedup vs baseline: 2.8308x; 1.8285x over previous
#include <cuda_runtime.h>
#include <math.h>
#include <stdint.h>

// Problem constants
#define D_MODEL 1024
#define NHEADS  16
#define HD      64
#define BATCH   4
#define SEQ     2048
#define MTOK    (BATCH * SEQ)   // 8192 rows

// Scratch (device globals: allocation inside kernel_launch is forbidden)
__device__ float g_qkv[(size_t)MTOK * 3 * D_MODEL];  // [8192, 3072]
__device__ float g_y  [(size_t)MTOK * D_MODEL];      // [8192, 1024]

// ---------------------------------------------------------------------------
// tf32 round-to-nearest (unbiased; avoids HMMA truncation bias)
// ---------------------------------------------------------------------------
__device__ __forceinline__ float tf32r(float x) {
    uint32_t o;
    asm("cvt.rna.tf32.f32 %0, %1;" : "=r"(o) : "f"(x));
    return __uint_as_float(o);
}

#define MMA_TF32(acc, a0, a1, a2, a3, b0, b1) \
    asm volatile( \
        "mma.sync.aligned.m16n8k8.row.col.f32.tf32.tf32.f32 " \
        "{%0,%1,%2,%3}, {%4,%5,%6,%7}, {%8,%9}, {%0,%1,%2,%3};" \
        : "+f"((acc)[0]), "+f"((acc)[1]), "+f"((acc)[2]), "+f"((acc)[3]) \
        : "r"(a0), "r"(a1), "r"(a2), "r"(a3), "r"(b0), "r"(b1))

// ---------------------------------------------------------------------------
// TF32 mma.sync GEMM: C[M,N] = A[M,K] @ B[K,N], row-major. (unchanged, known good)
// 128x128 CTA tile, BK=16, 8 warps (2x4), warp tile 64x32, double-buffered smem.
// ---------------------------------------------------------------------------
#define BK 16
#define AS_STRIDE 20
#define BS_STRIDE 136

__global__ __launch_bounds__(256, 2)
void gemm_tf32_mma(const float* __restrict__ A, const float* __restrict__ B,
                   float* __restrict__ C, int M, int N, int K)
{
    __shared__ __align__(16) float As[2][128][AS_STRIDE];
    __shared__ __align__(16) float Bs[2][BK][BS_STRIDE];

    const int tid = threadIdx.x;
    const int wid = tid >> 5, lane = tid & 31;
    const int wm = wid >> 2, wn = wid & 3;
    const int gId = lane >> 2, tig = lane & 3;
    const int bm = blockIdx.y, bn = blockIdx.x;

    const float* Ab = A + (size_t)(bm * 128) * K;
    const float* Bb = B + bn * 128;

    float acc[4][4][4];
#pragma unroll
    for (int i = 0; i < 4; i++)
#pragma unroll
        for (int j = 0; j < 4; j++)
#pragma unroll
            for (int r = 0; r < 4; r++) acc[i][j][r] = 0.0f;

    float4 av[2], bv[2];

    auto ldg = [&](int kt) {
#pragma unroll
        for (int i = 0; i < 2; i++) {
            int idx = tid + 256 * i;
            av[i] = *(const float4*)(Ab + (size_t)(idx >> 2) * K + kt * BK + (idx & 3) * 4);
            bv[i] = *(const float4*)(Bb + (size_t)(kt * BK + (idx >> 5)) * N + (idx & 31) * 4);
        }
    };
    auto sts = [&](int s) {
#pragma unroll
        for (int i = 0; i < 2; i++) {
            int idx = tid + 256 * i;
            int r = idx >> 2, kc = (idx & 3) * 4;
            As[s][r][kc + 0] = tf32r(av[i].x);
            As[s][r][kc + 1] = tf32r(av[i].y);
            As[s][r][kc + 2] = tf32r(av[i].z);
            As[s][r][kc + 3] = tf32r(av[i].w);
            int kr = idx >> 5, nc = (idx & 31) * 4;
            float4 b4 = make_float4(tf32r(bv[i].x), tf32r(bv[i].y),
                                    tf32r(bv[i].z), tf32r(bv[i].w));
            *(float4*)&Bs[s][kr][nc] = b4;
        }
    };
    auto compute = [&](int s) {
#pragma unroll
        for (int ks = 0; ks < 2; ks++) {
            const int kb = ks * 8;
            uint32_t a[4][4], b[4][2];
#pragma unroll
            for (int mf = 0; mf < 4; mf++) {
                int m0 = wm * 64 + mf * 16 + gId;
                a[mf][0] = __float_as_uint(As[s][m0][kb + tig]);
                a[mf][1] = __float_as_uint(As[s][m0 + 8][kb + tig]);
                a[mf][2] = __float_as_uint(As[s][m0][kb + tig + 4]);
                a[mf][3] = __float_as_uint(As[s][m0 + 8][kb + tig + 4]);
            }
#pragma unroll
            for (int nf = 0; nf < 4; nf++) {
                int n0 = wn * 32 + nf * 8 + gId;
                b[nf][0] = __float_as_uint(Bs[s][kb + tig][n0]);
                b[nf][1] = __float_as_uint(Bs[s][kb + tig + 4][n0]);
            }
#pragma unroll
            for (int mf = 0; mf < 4; mf++)
#pragma unroll
                for (int nf = 0; nf < 4; nf++)
                    MMA_TF32(acc[mf][nf], a[mf][0], a[mf][1], a[mf][2], a[mf][3],
                             b[nf][0], b[nf][1]);
        }
    };

    const int nkt = K / BK;
    ldg(0);
    sts(0);
    __syncthreads();
    for (int kt = 0; kt < nkt; kt++) {
        const int cur = kt & 1;
        const bool more = (kt + 1 < nkt);
        if (more) ldg(kt + 1);
        compute(cur);
        if (more) sts(cur ^ 1);
        __syncthreads();
    }

#pragma unroll
    for (int mf = 0; mf < 4; mf++) {
        int r0 = bm * 128 + wm * 64 + mf * 16 + gId;
#pragma unroll
        for (int nf = 0; nf < 4; nf++) {
            int c0 = bn * 128 + wn * 32 + nf * 8 + 2 * tig;
            *(float2*)&C[(size_t)r0 * N + c0] =
                make_float2(acc[mf][nf][0], acc[mf][nf][1]);
            *(float2*)&C[(size_t)(r0 + 8) * N + c0] =
                make_float2(acc[mf][nf][2], acc[mf][nf][3]);
        }
    }
}

// ---------------------------------------------------------------------------
// Flash attention with tf32 mma.sync (causal, online softmax).
// Block = 128-query tile of one (b,h). 8 warps; warp w owns query rows
// [w*16, w*16+16). Key tiles of 64. S and O accumulated via m16n8k8 mma;
// P re-shaped through per-warp smem (no block sync needed for P).
// Smem strides: Qs/Ks/Ps 68 (frag loads 4*gId+tig conflict-free),
//               Vs 72 (frag loads 8*tig+gId conflict-free).
// ---------------------------------------------------------------------------
#define QSTR 68
#define VSTR 72
#define FA_SMEM ((128 * QSTR + 64 * QSTR + 64 * VSTR + 128 * QSTR) * 4)

__global__ __launch_bounds__(256, 2)
void flash_attn_mma()
{
    extern __shared__ float sm[];
    float (*Qs)[QSTR] = (float(*)[QSTR])sm;                               // 128x68
    float (*Ks)[QSTR] = (float(*)[QSTR])(sm + 128 * QSTR);                // 64x68
    float (*Vs)[VSTR] = (float(*)[VSTR])(sm + 128 * QSTR + 64 * QSTR);    // 64x72
    float (*Ps)[QSTR] = (float(*)[QSTR])(sm + 128 * QSTR + 64 * QSTR + 64 * VSTR); // 128x68

    const int tid = threadIdx.x;
    const int wid = tid >> 5, lane = tid & 31;
    const int gId = lane >> 2, tig = lane & 3;
    const int b = blockIdx.z, h = blockIdx.y;
    const int qt = gridDim.x - 1 - blockIdx.x;   // heavy (large qt) blocks first
    const int q0 = qt * 128;
    const int r0 = wid * 16;

    // ---- load Q tile (scaled by 1/8, tf32-rounded) ----
#pragma unroll
    for (int i = 0; i < 8; i++) {
        int idx = tid + 256 * i;
        int row = idx >> 4, col = (idx & 15) * 4;
        const float* src = g_qkv + (size_t)(b * SEQ + q0 + row) * (3 * D_MODEL) + h * HD + col;
        float4 v = *(const float4*)src;
        Qs[row][col + 0] = tf32r(v.x * 0.125f);
        Qs[row][col + 1] = tf32r(v.y * 0.125f);
        Qs[row][col + 2] = tf32r(v.z * 0.125f);
        Qs[row][col + 3] = tf32r(v.w * 0.125f);
    }

    float accO[8][4];
#pragma unroll
    for (int nf = 0; nf < 8; nf++)
#pragma unroll
        for (int r = 0; r < 4; r++) accO[nf][r] = 0.0f;
    float mrow[2] = {-1e30f, -1e30f};
    float lrow[2] = {0.0f, 0.0f};

    const int ktiles = 2 * qt + 2;
    for (int jt = 0; jt < ktiles; jt++) {
        const int k0 = jt * 64;
        __syncthreads();   // all warps done reading previous Ks/Vs
        // ---- load K and V tiles ----
#pragma unroll
        for (int i = 0; i < 4; i++) {
            int idx = tid + 256 * i;
            int row = idx >> 4, col = (idx & 15) * 4;
            const float* kp = g_qkv + (size_t)(b * SEQ + k0 + row) * (3 * D_MODEL)
                              + D_MODEL + h * HD + col;
            float4 kv = *(const float4*)kp;
            float4 vv = *(const float4*)(kp + D_MODEL);
            Ks[row][col + 0] = tf32r(kv.x); Ks[row][col + 1] = tf32r(kv.y);
            Ks[row][col + 2] = tf32r(kv.z); Ks[row][col + 3] = tf32r(kv.w);
            Vs[row][col + 0] = tf32r(vv.x); Vs[row][col + 1] = tf32r(vv.y);
            Vs[row][col + 2] = tf32r(vv.z); Vs[row][col + 3] = tf32r(vv.w);
        }
        __syncthreads();

        // warps whose rows are entirely below this key tile: nothing to do
        if (k0 > q0 + r0 + 15) continue;

        // ---- S = Q @ K^T ----
        float accS[8][4];
#pragma unroll
        for (int nf = 0; nf < 8; nf++)
#pragma unroll
            for (int r = 0; r < 4; r++) accS[nf][r] = 0.0f;

#pragma unroll
        for (int ks = 0; ks < 8; ks++) {
            const int kb = ks * 8;
            uint32_t a0 = __float_as_uint(Qs[r0 + gId][kb + tig]);
            uint32_t a1 = __float_as_uint(Qs[r0 + gId + 8][kb + tig]);
            uint32_t a2 = __float_as_uint(Qs[r0 + gId][kb + tig + 4]);
            uint32_t a3 = __float_as_uint(Qs[r0 + gId + 8][kb + tig + 4]);
#pragma unroll
            for (int nf = 0; nf < 8; nf++) {
                uint32_t b0 = __float_as_uint(Ks[nf * 8 + gId][kb + tig]);
                uint32_t b1 = __float_as_uint(Ks[nf * 8 + gId][kb + tig + 4]);
                MMA_TF32(accS[nf], a0, a1, a2, a3, b0, b1);
            }
        }

        // ---- causal mask (only near the diagonal) ----
        if (k0 + 63 > q0 + r0) {
            const int rlo = q0 + r0 + gId, rhi = rlo + 8;
#pragma unroll
            for (int nf = 0; nf < 8; nf++) {
                int cg = k0 + nf * 8 + 2 * tig;
                if (cg > rlo)     accS[nf][0] = -1e30f;
                if (cg + 1 > rlo) accS[nf][1] = -1e30f;
                if (cg > rhi)     accS[nf][2] = -1e30f;
                if (cg + 1 > rhi) accS[nf][3] = -1e30f;
            }
        }

        // ---- online softmax (rows gId and gId+8; quad-lane reduction) ----
#pragma unroll
        for (int r = 0; r < 2; r++) {
            float vmax = -1e30f;
#pragma unroll
            for (int nf = 0; nf < 8; nf++)
                vmax = fmaxf(vmax, fmaxf(accS[nf][2 * r], accS[nf][2 * r + 1]));
            vmax = fmaxf(vmax, __shfl_xor_sync(0xffffffffu, vmax, 1));
            vmax = fmaxf(vmax, __shfl_xor_sync(0xffffffffu, vmax, 2));
            float mnew = fmaxf(mrow[r], vmax);
            float sum = 0.0f;
#pragma unroll
            for (int nf = 0; nf < 8; nf++) {
                accS[nf][2 * r]     = __expf(accS[nf][2 * r] - mnew);
                accS[nf][2 * r + 1] = __expf(accS[nf][2 * r + 1] - mnew);
                sum += accS[nf][2 * r] + accS[nf][2 * r + 1];
            }
            sum += __shfl_xor_sync(0xffffffffu, sum, 1);
            sum += __shfl_xor_sync(0xffffffffu, sum, 2);
            float alpha = __expf(mrow[r] - mnew);
            lrow[r] = lrow[r] * alpha + sum;
            mrow[r] = mnew;
#pragma unroll
            for (int nf = 0; nf < 8; nf++) {
                accO[nf][2 * r]     *= alpha;
                accO[nf][2 * r + 1] *= alpha;
            }
        }

        // ---- P -> per-warp smem (re-shape C-frag -> A-frag layout) ----
        __syncwarp();   // previous PV reads of Ps complete before overwrite
#pragma unroll
        for (int nf = 0; nf < 8; nf++) {
            *(float2*)&Ps[r0 + gId][nf * 8 + 2 * tig] =
                make_float2(accS[nf][0], accS[nf][1]);
            *(float2*)&Ps[r0 + gId + 8][nf * 8 + 2 * tig] =
                make_float2(accS[nf][2], accS[nf][3]);
        }
        __syncwarp();

        // ---- O += P @ V ----
#pragma unroll
        for (int ks = 0; ks < 8; ks++) {
            const int kb = ks * 8;
            uint32_t a0 = __float_as_uint(Ps[r0 + gId][kb + tig]);
            uint32_t a1 = __float_as_uint(Ps[r0 + gId + 8][kb + tig]);
            uint32_t a2 = __float_as_uint(Ps[r0 + gId][kb + tig + 4]);
            uint32_t a3 = __float_as_uint(Ps[r0 + gId + 8][kb + tig + 4]);
#pragma unroll
            for (int nf = 0; nf < 8; nf++) {
                uint32_t b0 = __float_as_uint(Vs[kb + tig][nf * 8 + gId]);
                uint32_t b1 = __float_as_uint(Vs[kb + tig + 4][nf * 8 + gId]);
                MMA_TF32(accO[nf], a0, a1, a2, a3, b0, b1);
            }
        }
    }

    // ---- epilogue: normalize and write y[b,s,h,hd] ----
    const float inv0 = 1.0f / lrow[0];
    const float inv1 = 1.0f / lrow[1];
    const size_t rlo = (size_t)(b * SEQ + q0 + r0 + gId);
#pragma unroll
    for (int nf = 0; nf < 8; nf++) {
        int col = h * HD + nf * 8 + 2 * tig;
        *(float2*)&g_y[rlo * D_MODEL + col] =
            make_float2(accO[nf][0] * inv0, accO[nf][1] * inv0);
        *(float2*)&g_y[(rlo + 8) * D_MODEL + col] =
            make_float2(accO[nf][2] * inv1, accO[nf][3] * inv1);
    }
}

// ---------------------------------------------------------------------------
extern "C" void kernel_launch(void* const* d_in, const int* in_sizes, int n_in,
                              void* d_out, int out_size)
{
    const float* x      = (const float*)d_in[0];   // [4,2048,1024]
    const float* w_qkv  = (const float*)d_in[1];   // [1024,3072]
    const float* w_proj = (const float*)d_in[2];   // [1024,1024]
    float* out = (float*)d_out;                    // [4,2048,1024]

    float *qkv_ptr, *y_ptr;
    cudaGetSymbolAddress((void**)&qkv_ptr, g_qkv);
    cudaGetSymbolAddress((void**)&y_ptr, g_y);

    cudaFuncSetAttribute(flash_attn_mma,
                         cudaFuncAttributeMaxDynamicSharedMemorySize, FA_SMEM);

    // 1) qkv = x @ w_qkv   [8192,1024] @ [1024,3072]  (tf32 mma.sync)
    gemm_tf32_mma<<<dim3(3 * D_MODEL / 128, MTOK / 128), 256>>>(
        x, w_qkv, qkv_ptr, MTOK, 3 * D_MODEL, D_MODEL);

    // 2) flash attention (tf32 mma) -> g_y [8192,1024]
    flash_attn_mma<<<dim3(SEQ / 128, NHEADS, BATCH), 256, FA_SMEM>>>();

    // 3) out = y @ w_proj  [8192,1024] @ [1024,1024]  (tf32 mma.sync)
    gemm_tf32_mma<<<dim3(D_MODEL / 128, MTOK / 128), 256>>>(
        y_ptr, w_proj, out, MTOK, D_MODEL, D_MODEL);
}

// round 6
// speedup vs baseline: 2.9751x; 1.0510x over previous
#include <cuda_runtime.h>
#include <math.h>
#include <stdint.h>

// Problem constants
#define D_MODEL 1024
#define NHEADS  16
#define HD      64
#define BATCH   4
#define SEQ     2048
#define MTOK    (BATCH * SEQ)   // 8192 rows

// Scratch (device globals: allocation inside kernel_launch is forbidden)
__device__ float g_qkv[(size_t)MTOK * 3 * D_MODEL];     // [8192, 3072]
__device__ float g_y  [(size_t)MTOK * D_MODEL];         // [8192, 1024] (tf32-rounded)
__device__ float g_xr [(size_t)MTOK * D_MODEL];         // tf32-rounded x
__device__ float g_wqkvr[(size_t)D_MODEL * 3 * D_MODEL];// tf32-rounded w_qkv
__device__ float g_wprojr[(size_t)D_MODEL * D_MODEL];   // tf32-rounded w_proj

// ---------------------------------------------------------------------------
__device__ __forceinline__ float tf32r(float x) {
    uint32_t o;
    asm("cvt.rna.tf32.f32 %0, %1;" : "=r"(o) : "f"(x));
    return __uint_as_float(o);
}

#define MMA_TF32(acc, a0, a1, a2, a3, b0, b1) \
    asm volatile( \
        "mma.sync.aligned.m16n8k8.row.col.f32.tf32.tf32.f32 " \
        "{%0,%1,%2,%3}, {%4,%5,%6,%7}, {%8,%9}, {%0,%1,%2,%3};" \
        : "+f"((acc)[0]), "+f"((acc)[1]), "+f"((acc)[2]), "+f"((acc)[3]) \
        : "r"(a0), "r"(a1), "r"(a2), "r"(a3), "r"(b0), "r"(b1))

__device__ __forceinline__ uint32_t smem_u32(const void* p) {
    uint32_t a;
    asm("{ .reg .u64 t; cvta.to.shared.u64 t, %1; cvt.u32.u64 %0, t; }" : "=r"(a) : "l"(p));
    return a;
}
__device__ __forceinline__ void cp_async16(uint32_t dst, const void* src) {
    asm volatile("cp.async.cg.shared.global [%0], [%1], 16;" :: "r"(dst), "l"(src));
}
#define CP_COMMIT() asm volatile("cp.async.commit_group;" ::: "memory")
#define CP_WAIT_GROUP(n) asm volatile("cp.async.wait_group %0;" :: "n"(n) : "memory")

// ---------------------------------------------------------------------------
// tf32 rounding prepass (vectorized)
// ---------------------------------------------------------------------------
__global__ void round_tf32_kernel(const float* __restrict__ in, float* __restrict__ out, int n4)
{
    int i = blockIdx.x * blockDim.x + threadIdx.x;
    if (i < n4) {
        float4 v = ((const float4*)in)[i];
        ((float4*)out)[i] = make_float4(tf32r(v.x), tf32r(v.y), tf32r(v.z), tf32r(v.w));
    }
}

// ---------------------------------------------------------------------------
// TF32 mma.sync GEMM v2: C[M,N] = A[M,K] @ B[K,N], row-major, pre-rounded inputs.
// 128x128 CTA tile, BK=32, 3-stage cp.async pipeline, 8 warps (2x4),
// warp tile 64x32. A smem [m][36] (a-frag bank = lane), B smem [k][136]
// (b-frag banks 8*tig+8*nf+gId) — both conflict-free.
// ---------------------------------------------------------------------------
#define GBK 32
#define GSTAGES 3
#define A_STR 36
#define B_STR 136
#define STAGE_FLOATS (128 * A_STR + GBK * B_STR)   // 4608 + 4352 = 8960
#define GEMM_SMEM (GSTAGES * STAGE_FLOATS * 4)     // 107520 B

__global__ __launch_bounds__(256)
void gemm_tf32_v2(const float* __restrict__ A, const float* __restrict__ B,
                  float* __restrict__ C, int M, int N, int K)
{
    extern __shared__ float sm[];
    const uint32_t sbase = smem_u32(sm);

    const int tid = threadIdx.x;
    const int wid = tid >> 5, lane = tid & 31;
    const int wm = wid >> 2, wn = wid & 3;
    const int gId = lane >> 2, tig = lane & 3;
    const int bm = blockIdx.y, bn = blockIdx.x;

    const float* Ab = A + (size_t)(bm * 128) * K;
    const float* Bb = B + bn * 128;

    float acc[4][4][4];
#pragma unroll
    for (int i = 0; i < 4; i++)
#pragma unroll
        for (int j = 0; j < 4; j++)
#pragma unroll
            for (int r = 0; r < 4; r++) acc[i][j][r] = 0.0f;

    // async load of K-chunk kt into stage s
    auto load_stage = [&](int kt, int s) {
        const uint32_t aT = sbase + (uint32_t)(s * STAGE_FLOATS) * 4;
        const uint32_t bT = aT + 128 * A_STR * 4;
        const int k0 = kt * GBK;
#pragma unroll
        for (int i = 0; i < 4; i++) {          // A: 1024 chunks of 16B
            int c = tid + 256 * i;
            int row = c >> 3, kc = (c & 7) * 4;
            cp_async16(aT + (uint32_t)(row * A_STR + kc) * 4,
                       Ab + (size_t)row * K + k0 + kc);
        }
#pragma unroll
        for (int i = 0; i < 4; i++) {          // B: 1024 chunks of 16B
            int c = tid + 256 * i;
            int row = c >> 5, nc = (c & 31) * 4;
            cp_async16(bT + (uint32_t)(row * B_STR + nc) * 4,
                       Bb + (size_t)(k0 + row) * N + nc);
        }
    };

    auto compute = [&](int s) {
        const float* As = sm + s * STAGE_FLOATS;
        const float* Bs = As + 128 * A_STR;
#pragma unroll
        for (int ks = 0; ks < 4; ks++) {
            const int kb = ks * 8;
            uint32_t a[4][4], b[4][2];
#pragma unroll
            for (int mf = 0; mf < 4; mf++) {
                int m0 = wm * 64 + mf * 16 + gId;
                a[mf][0] = __float_as_uint(As[m0 * A_STR + kb + tig]);
                a[mf][1] = __float_as_uint(As[(m0 + 8) * A_STR + kb + tig]);
                a[mf][2] = __float_as_uint(As[m0 * A_STR + kb + tig + 4]);
                a[mf][3] = __float_as_uint(As[(m0 + 8) * A_STR + kb + tig + 4]);
            }
#pragma unroll
            for (int nf = 0; nf < 4; nf++) {
                int n0 = wn * 32 + nf * 8 + gId;
                b[nf][0] = __float_as_uint(Bs[(kb + tig) * B_STR + n0]);
                b[nf][1] = __float_as_uint(Bs[(kb + tig + 4) * B_STR + n0]);
            }
#pragma unroll
            for (int mf = 0; mf < 4; mf++)
#pragma unroll
                for (int nf = 0; nf < 4; nf++)
                    MMA_TF32(acc[mf][nf], a[mf][0], a[mf][1], a[mf][2], a[mf][3],
                             b[nf][0], b[nf][1]);
        }
    };

    const int nkt = K / GBK;
    load_stage(0, 0); CP_COMMIT();
    load_stage(1, 1); CP_COMMIT();

    for (int kt = 0; kt < nkt; kt++) {
        CP_WAIT_GROUP(1);        // stage kt resident
        __syncthreads();         // all warps done with stage being overwritten
        if (kt + 2 < nkt) load_stage(kt + 2, (kt + 2) % GSTAGES);
        CP_COMMIT();             // empty commit in tail keeps group counting valid
        compute(kt % GSTAGES);
    }

#pragma unroll
    for (int mf = 0; mf < 4; mf++) {
        int r0 = bm * 128 + wm * 64 + mf * 16 + gId;
#pragma unroll
        for (int nf = 0; nf < 4; nf++) {
            int c0 = bn * 128 + wn * 32 + nf * 8 + 2 * tig;
            *(float2*)&C[(size_t)r0 * N + c0] =
                make_float2(acc[mf][nf][0], acc[mf][nf][1]);
            *(float2*)&C[(size_t)(r0 + 8) * N + c0] =
                make_float2(acc[mf][nf][2], acc[mf][nf][3]);
        }
    }
}

// ---------------------------------------------------------------------------
// Flash attention with tf32 mma.sync (causal, online softmax). Unchanged
// except the epilogue tf32-rounds y (feeds the pre-rounded-input proj GEMM).
// ---------------------------------------------------------------------------
#define QSTR 68
#define VSTR 72
#define FA_SMEM ((128 * QSTR + 64 * QSTR + 64 * VSTR + 128 * QSTR) * 4)

__global__ __launch_bounds__(256, 2)
void flash_attn_mma()
{
    extern __shared__ float smf[];
    float (*Qs)[QSTR] = (float(*)[QSTR])smf;
    float (*Ks)[QSTR] = (float(*)[QSTR])(smf + 128 * QSTR);
    float (*Vs)[VSTR] = (float(*)[VSTR])(smf + 128 * QSTR + 64 * QSTR);
    float (*Ps)[QSTR] = (float(*)[QSTR])(smf + 128 * QSTR + 64 * QSTR + 64 * VSTR);

    const int tid = threadIdx.x;
    const int wid = tid >> 5, lane = tid & 31;
    const int gId = lane >> 2, tig = lane & 3;
    const int b = blockIdx.z, h = blockIdx.y;
    const int qt = gridDim.x - 1 - blockIdx.x;
    const int q0 = qt * 128;
    const int r0 = wid * 16;

#pragma unroll
    for (int i = 0; i < 8; i++) {
        int idx = tid + 256 * i;
        int row = idx >> 4, col = (idx & 15) * 4;
        const float* src = g_qkv + (size_t)(b * SEQ + q0 + row) * (3 * D_MODEL) + h * HD + col;
        float4 v = *(const float4*)src;
        Qs[row][col + 0] = tf32r(v.x * 0.125f);
        Qs[row][col + 1] = tf32r(v.y * 0.125f);
        Qs[row][col + 2] = tf32r(v.z * 0.125f);
        Qs[row][col + 3] = tf32r(v.w * 0.125f);
    }

    float accO[8][4];
#pragma unroll
    for (int nf = 0; nf < 8; nf++)
#pragma unroll
        for (int r = 0; r < 4; r++) accO[nf][r] = 0.0f;
    float mrow[2] = {-1e30f, -1e30f};
    float lrow[2] = {0.0f, 0.0f};

    const int ktiles = 2 * qt + 2;
    for (int jt = 0; jt < ktiles; jt++) {
        const int k0 = jt * 64;
        __syncthreads();
#pragma unroll
        for (int i = 0; i < 4; i++) {
            int idx = tid + 256 * i;
            int row = idx >> 4, col = (idx & 15) * 4;
            const float* kp = g_qkv + (size_t)(b * SEQ + k0 + row) * (3 * D_MODEL)
                              + D_MODEL + h * HD + col;
            float4 kv = *(const float4*)kp;
            float4 vv = *(const float4*)(kp + D_MODEL);
            Ks[row][col + 0] = tf32r(kv.x); Ks[row][col + 1] = tf32r(kv.y);
            Ks[row][col + 2] = tf32r(kv.z); Ks[row][col + 3] = tf32r(kv.w);
            Vs[row][col + 0] = tf32r(vv.x); Vs[row][col + 1] = tf32r(vv.y);
            Vs[row][col + 2] = tf32r(vv.z); Vs[row][col + 3] = tf32r(vv.w);
        }
        __syncthreads();

        if (k0 > q0 + r0 + 15) continue;

        float accS[8][4];
#pragma unroll
        for (int nf = 0; nf < 8; nf++)
#pragma unroll
            for (int r = 0; r < 4; r++) accS[nf][r] = 0.0f;

#pragma unroll
        for (int ks = 0; ks < 8; ks++) {
            const int kb = ks * 8;
            uint32_t a0 = __float_as_uint(Qs[r0 + gId][kb + tig]);
            uint32_t a1 = __float_as_uint(Qs[r0 + gId + 8][kb + tig]);
            uint32_t a2 = __float_as_uint(Qs[r0 + gId][kb + tig + 4]);
            uint32_t a3 = __float_as_uint(Qs[r0 + gId + 8][kb + tig + 4]);
#pragma unroll
            for (int nf = 0; nf < 8; nf++) {
                uint32_t b0 = __float_as_uint(Ks[nf * 8 + gId][kb + tig]);
                uint32_t b1 = __float_as_uint(Ks[nf * 8 + gId][kb + tig + 4]);
                MMA_TF32(accS[nf], a0, a1, a2, a3, b0, b1);
            }
        }

        if (k0 + 63 > q0 + r0) {
            const int rlo = q0 + r0 + gId, rhi = rlo + 8;
#pragma unroll
            for (int nf = 0; nf < 8; nf++) {
                int cg = k0 + nf * 8 + 2 * tig;
                if (cg > rlo)     accS[nf][0] = -1e30f;
                if (cg + 1 > rlo) accS[nf][1] = -1e30f;
                if (cg > rhi)     accS[nf][2] = -1e30f;
                if (cg + 1 > rhi) accS[nf][3] = -1e30f;
            }
        }

#pragma unroll
        for (int r = 0; r < 2; r++) {
            float vmax = -1e30f;
#pragma unroll
            for (int nf = 0; nf < 8; nf++)
                vmax = fmaxf(vmax, fmaxf(accS[nf][2 * r], accS[nf][2 * r + 1]));
            vmax = fmaxf(vmax, __shfl_xor_sync(0xffffffffu, vmax, 1));
            vmax = fmaxf(vmax, __shfl_xor_sync(0xffffffffu, vmax, 2));
            float mnew = fmaxf(mrow[r], vmax);
            float sum = 0.0f;
#pragma unroll
            for (int nf = 0; nf < 8; nf++) {
                accS[nf][2 * r]     = __expf(accS[nf][2 * r] - mnew);
                accS[nf][2 * r + 1] = __expf(accS[nf][2 * r + 1] - mnew);
                sum += accS[nf][2 * r] + accS[nf][2 * r + 1];
            }
            sum += __shfl_xor_sync(0xffffffffu, sum, 1);
            sum += __shfl_xor_sync(0xffffffffu, sum, 2);
            float alpha = __expf(mrow[r] - mnew);
            lrow[r] = lrow[r] * alpha + sum;
            mrow[r] = mnew;
#pragma unroll
            for (int nf = 0; nf < 8; nf++) {
                accO[nf][2 * r]     *= alpha;
                accO[nf][2 * r + 1] *= alpha;
            }
        }

        __syncwarp();
#pragma unroll
        for (int nf = 0; nf < 8; nf++) {
            *(float2*)&Ps[r0 + gId][nf * 8 + 2 * tig] =
                make_float2(accS[nf][0], accS[nf][1]);
            *(float2*)&Ps[r0 + gId + 8][nf * 8 + 2 * tig] =
                make_float2(accS[nf][2], accS[nf][3]);
        }
        __syncwarp();

#pragma unroll
        for (int ks = 0; ks < 8; ks++) {
            const int kb = ks * 8;
            uint32_t a0 = __float_as_uint(Ps[r0 + gId][kb + tig]);
            uint32_t a1 = __float_as_uint(Ps[r0 + gId + 8][kb + tig]);
            uint32_t a2 = __float_as_uint(Ps[r0 + gId][kb + tig + 4]);
            uint32_t a3 = __float_as_uint(Ps[r0 + gId + 8][kb + tig + 4]);
#pragma unroll
            for (int nf = 0; nf < 8; nf++) {
                uint32_t b0 = __float_as_uint(Vs[kb + tig][nf * 8 + gId]);
                uint32_t b1 = __float_as_uint(Vs[kb + tig + 4][nf * 8 + gId]);
                MMA_TF32(accO[nf], a0, a1, a2, a3, b0, b1);
            }
        }
    }

    // epilogue: normalize, tf32-round (proj GEMM input), write y
    const float inv0 = 1.0f / lrow[0];
    const float inv1 = 1.0f / lrow[1];
    const size_t rlo = (size_t)(b * SEQ + q0 + r0 + gId);
#pragma unroll
    for (int nf = 0; nf < 8; nf++) {
        int col = h * HD + nf * 8 + 2 * tig;
        *(float2*)&g_y[rlo * D_MODEL + col] =
            make_float2(tf32r(accO[nf][0] * inv0), tf32r(accO[nf][1] * inv0));
        *(float2*)&g_y[(rlo + 8) * D_MODEL + col] =
            make_float2(tf32r(accO[nf][2] * inv1), tf32r(accO[nf][3] * inv1));
    }
}

// ---------------------------------------------------------------------------
extern "C" void kernel_launch(void* const* d_in, const int* in_sizes, int n_in,
                              void* d_out, int out_size)
{
    const float* x      = (const float*)d_in[0];   // [4,2048,1024]
    const float* w_qkv  = (const float*)d_in[1];   // [1024,3072]
    const float* w_proj = (const float*)d_in[2];   // [1024,1024]
    float* out = (float*)d_out;                    // [4,2048,1024]

    float *qkv_ptr, *y_ptr, *xr_ptr, *wqkvr_ptr, *wprojr_ptr;
    cudaGetSymbolAddress((void**)&qkv_ptr, g_qkv);
    cudaGetSymbolAddress((void**)&y_ptr, g_y);
    cudaGetSymbolAddress((void**)&xr_ptr, g_xr);
    cudaGetSymbolAddress((void**)&wqkvr_ptr, g_wqkvr);
    cudaGetSymbolAddress((void**)&wprojr_ptr, g_wprojr);

    cudaFuncSetAttribute(gemm_tf32_v2,
                         cudaFuncAttributeMaxDynamicSharedMemorySize, GEMM_SMEM);
    cudaFuncSetAttribute(flash_attn_mma,
                         cudaFuncAttributeMaxDynamicSharedMemorySize, FA_SMEM);

    // 0) tf32-round inputs (prepass)
    {
        int n4;
        n4 = MTOK * D_MODEL / 4;
        round_tf32_kernel<<<(n4 + 255) / 256, 256>>>(x, xr_ptr, n4);
        n4 = D_MODEL * 3 * D_MODEL / 4;
        round_tf32_kernel<<<(n4 + 255) / 256, 256>>>(w_qkv, wqkvr_ptr, n4);
        n4 = D_MODEL * D_MODEL / 4;
        round_tf32_kernel<<<(n4 + 255) / 256, 256>>>(w_proj, wprojr_ptr, n4);
    }

    // 1) qkv = x @ w_qkv   (tf32 mma, cp.async 3-stage)
    gemm_tf32_v2<<<dim3(3 * D_MODEL / 128, MTOK / 128), 256, GEMM_SMEM>>>(
        xr_ptr, wqkvr_ptr, qkv_ptr, MTOK, 3 * D_MODEL, D_MODEL);

    // 2) flash attention (tf32 mma) -> g_y (rounded)
    flash_attn_mma<<<dim3(SEQ / 128, NHEADS, BATCH), 256, FA_SMEM>>>();

    // 3) out = y @ w_proj  (tf32 mma, cp.async 3-stage)
    gemm_tf32_v2<<<dim3(D_MODEL / 128, MTOK / 128), 256, GEMM_SMEM>>>(
        y_ptr, wprojr_ptr, out, MTOK, D_MODEL, D_MODEL);
}

// round 9
// speedup vs baseline: 3.1498x; 1.0587x over previous
#include <cuda_runtime.h>
#include <math.h>
#include <stdint.h>

// Problem constants
#define D_MODEL 1024
#define NHEADS  16
#define HD      64
#define BATCH   4
#define SEQ     2048
#define MTOK    (BATCH * SEQ)   // 8192 rows

// Scratch (device globals: allocation inside kernel_launch is forbidden)
__device__ float g_qkv[(size_t)MTOK * 3 * D_MODEL];     // [8192, 3072]
__device__ float g_y  [(size_t)MTOK * D_MODEL];         // [8192, 1024] (tf32-rounded)
__device__ float g_xr [(size_t)MTOK * D_MODEL];         // tf32-rounded x
__device__ float g_wqkvr[(size_t)D_MODEL * 3 * D_MODEL];// tf32-rounded w_qkv
__device__ float g_wprojr[(size_t)D_MODEL * D_MODEL];   // tf32-rounded w_proj

// ---------------------------------------------------------------------------
__device__ __forceinline__ float tf32r(float x) {
    uint32_t o;
    asm("cvt.rna.tf32.f32 %0, %1;" : "=r"(o) : "f"(x));
    return __uint_as_float(o);
}

#define MMA_TF32(acc, a0, a1, a2, a3, b0, b1) \
    asm volatile( \
        "mma.sync.aligned.m16n8k8.row.col.f32.tf32.tf32.f32 " \
        "{%0,%1,%2,%3}, {%4,%5,%6,%7}, {%8,%9}, {%0,%1,%2,%3};" \
        : "+f"((acc)[0]), "+f"((acc)[1]), "+f"((acc)[2]), "+f"((acc)[3]) \
        : "r"(a0), "r"(a1), "r"(a2), "r"(a3), "r"(b0), "r"(b1))

__device__ __forceinline__ uint32_t smem_u32(const void* p) {
    uint32_t a;
    asm("{ .reg .u64 t; cvta.to.shared.u64 t, %1; cvt.u32.u64 %0, t; }" : "=r"(a) : "l"(p));
    return a;
}
__device__ __forceinline__ void cp_async16(uint32_t dst, const void* src) {
    asm volatile("cp.async.cg.shared.global [%0], [%1], 16;" :: "r"(dst), "l"(src));
}
#define CP_COMMIT() asm volatile("cp.async.commit_group;" ::: "memory")
#define CP_WAIT_GROUP(n) asm volatile("cp.async.wait_group %0;" :: "n"(n) : "memory")

// ---------------------------------------------------------------------------
// tf32 rounding prepass (vectorized)
// ---------------------------------------------------------------------------
__global__ void round_tf32_kernel(const float* __restrict__ in, float* __restrict__ out, int n4)
{
    int i = blockIdx.x * blockDim.x + threadIdx.x;
    if (i < n4) {
        float4 v = ((const float4*)in)[i];
        ((float4*)out)[i] = make_float4(tf32r(v.x), tf32r(v.y), tf32r(v.z), tf32r(v.w));
    }
}

// ---------------------------------------------------------------------------
// TF32 mma.sync GEMM v2.1: C[M,N] = A[M,K] @ B[K,N], row-major, pre-rounded.
// 128x128 CTA tile, BK=32, 3-stage cp.async pipeline, 8 warps (2x4),
// warp tile 64x32. __launch_bounds__(256,2): cap 128 regs -> 2 CTAs/SM
// (215KB smem fits the 227KB carveout) for cross-CTA latency hiding.
// ---------------------------------------------------------------------------
#define GBK 32
#define GSTAGES 3
#define A_STR 36
#define B_STR 136
#define STAGE_FLOATS (128 * A_STR + GBK * B_STR)   // 4608 + 4352 = 8960
#define GEMM_SMEM (GSTAGES * STAGE_FLOATS * 4)     // 107520 B

__global__ __launch_bounds__(256, 2)
void gemm_tf32_v2(const float* __restrict__ A, const float* __restrict__ B,
                  float* __restrict__ C, int M, int N, int K)
{
    extern __shared__ float sm[];
    const uint32_t sbase = smem_u32(sm);

    const int tid = threadIdx.x;
    const int wid = tid >> 5, lane = tid & 31;
    const int wm = wid >> 2, wn = wid & 3;
    const int gId = lane >> 2, tig = lane & 3;
    const int bm = blockIdx.y, bn = blockIdx.x;

    const float* Ab = A + (size_t)(bm * 128) * K;
    const float* Bb = B + bn * 128;

    float acc[4][4][4];
#pragma unroll
    for (int i = 0; i < 4; i++)
#pragma unroll
        for (int j = 0; j < 4; j++)
#pragma unroll
            for (int r = 0; r < 4; r++) acc[i][j][r] = 0.0f;

    // async load of K-chunk kt into stage s
    auto load_stage = [&](int kt, int s) {
        const uint32_t aT = sbase + (uint32_t)(s * STAGE_FLOATS) * 4;
        const uint32_t bT = aT + 128 * A_STR * 4;
        const int k0 = kt * GBK;
#pragma unroll
        for (int i = 0; i < 4; i++) {          // A: 1024 chunks of 16B
            int c = tid + 256 * i;
            int row = c >> 3, kc = (c & 7) * 4;
            cp_async16(aT + (uint32_t)(row * A_STR + kc) * 4,
                       Ab + (size_t)row * K + k0 + kc);
        }
#pragma unroll
        for (int i = 0; i < 4; i++) {          // B: 1024 chunks of 16B
            int c = tid + 256 * i;
            int row = c >> 5, nc = (c & 31) * 4;
            cp_async16(bT + (uint32_t)(row * B_STR + nc) * 4,
                       Bb + (size_t)(k0 + row) * N + nc);
        }
    };

    auto compute = [&](int s) {
        const float* As = sm + s * STAGE_FLOATS;
        const float* Bs = As + 128 * A_STR;
#pragma unroll
        for (int ks = 0; ks < 4; ks++) {
            const int kb = ks * 8;
            uint32_t a[4][4], b[4][2];
#pragma unroll
            for (int mf = 0; mf < 4; mf++) {
                int m0 = wm * 64 + mf * 16 + gId;
                a[mf][0] = __float_as_uint(As[m0 * A_STR + kb + tig]);
                a[mf][1] = __float_as_uint(As[(m0 + 8) * A_STR + kb + tig]);
                a[mf][2] = __float_as_uint(As[m0 * A_STR + kb + tig + 4]);
                a[mf][3] = __float_as_uint(As[(m0 + 8) * A_STR + kb + tig + 4]);
            }
#pragma unroll
            for (int nf = 0; nf < 4; nf++) {
                int n0 = wn * 32 + nf * 8 + gId;
                b[nf][0] = __float_as_uint(Bs[(kb + tig) * B_STR + n0]);
                b[nf][1] = __float_as_uint(Bs[(kb + tig + 4) * B_STR + n0]);
            }
#pragma unroll
            for (int mf = 0; mf < 4; mf++)
#pragma unroll
                for (int nf = 0; nf < 4; nf++)
                    MMA_TF32(acc[mf][nf], a[mf][0], a[mf][1], a[mf][2], a[mf][3],
                             b[nf][0], b[nf][1]);
        }
    };

    const int nkt = K / GBK;
    load_stage(0, 0); CP_COMMIT();
    load_stage(1, 1); CP_COMMIT();

    for (int kt = 0; kt < nkt; kt++) {
        CP_WAIT_GROUP(1);        // stage kt resident
        __syncthreads();         // all warps done with stage being overwritten
        if (kt + 2 < nkt) load_stage(kt + 2, (kt + 2) % GSTAGES);
        CP_COMMIT();             // empty commit in tail keeps group counting valid
        compute(kt % GSTAGES);
    }

#pragma unroll
    for (int mf = 0; mf < 4; mf++) {
        int r0 = bm * 128 + wm * 64 + mf * 16 + gId;
#pragma unroll
        for (int nf = 0; nf < 4; nf++) {
            int c0 = bn * 128 + wn * 32 + nf * 8 + 2 * tig;
            *(float2*)&C[(size_t)r0 * N + c0] =
                make_float2(acc[mf][nf][0], acc[mf][nf][1]);
            *(float2*)&C[(size_t)(r0 + 8) * N + c0] =
                make_float2(acc[mf][nf][2], acc[mf][nf][3]);
        }
    }
}

// ---------------------------------------------------------------------------
// Flash attention with tf32 mma.sync (causal, online softmax). Unchanged.
// ---------------------------------------------------------------------------
#define QSTR 68
#define VSTR 72
#define FA_SMEM ((128 * QSTR + 64 * QSTR + 64 * VSTR + 128 * QSTR) * 4)

__global__ __launch_bounds__(256, 2)
void flash_attn_mma()
{
    extern __shared__ float smf[];
    float (*Qs)[QSTR] = (float(*)[QSTR])smf;
    float (*Ks)[QSTR] = (float(*)[QSTR])(smf + 128 * QSTR);
    float (*Vs)[VSTR] = (float(*)[VSTR])(smf + 128 * QSTR + 64 * QSTR);
    float (*Ps)[QSTR] = (float(*)[QSTR])(smf + 128 * QSTR + 64 * QSTR + 64 * VSTR);

    const int tid = threadIdx.x;
    const int wid = tid >> 5, lane = tid & 31;
    const int gId = lane >> 2, tig = lane & 3;
    const int b = blockIdx.z, h = blockIdx.y;
    const int qt = gridDim.x - 1 - blockIdx.x;
    const int q0 = qt * 128;
    const int r0 = wid * 16;

#pragma unroll
    for (int i = 0; i < 8; i++) {
        int idx = tid + 256 * i;
        int row = idx >> 4, col = (idx & 15) * 4;
        const float* src = g_qkv + (size_t)(b * SEQ + q0 + row) * (3 * D_MODEL) + h * HD + col;
        float4 v = *(const float4*)src;
        Qs[row][col + 0] = tf32r(v.x * 0.125f);
        Qs[row][col + 1] = tf32r(v.y * 0.125f);
        Qs[row][col + 2] = tf32r(v.z * 0.125f);
        Qs[row][col + 3] = tf32r(v.w * 0.125f);
    }

    float accO[8][4];
#pragma unroll
    for (int nf = 0; nf < 8; nf++)
#pragma unroll
        for (int r = 0; r < 4; r++) accO[nf][r] = 0.0f;
    float mrow[2] = {-1e30f, -1e30f};
    float lrow[2] = {0.0f, 0.0f};

    const int ktiles = 2 * qt + 2;
    for (int jt = 0; jt < ktiles; jt++) {
        const int k0 = jt * 64;
        __syncthreads();
#pragma unroll
        for (int i = 0; i < 4; i++) {
            int idx = tid + 256 * i;
            int row = idx >> 4, col = (idx & 15) * 4;
            const float* kp = g_qkv + (size_t)(b * SEQ + k0 + row) * (3 * D_MODEL)
                              + D_MODEL + h * HD + col;
            float4 kv = *(const float4*)kp;
            float4 vv = *(const float4*)(kp + D_MODEL);
            Ks[row][col + 0] = tf32r(kv.x); Ks[row][col + 1] = tf32r(kv.y);
            Ks[row][col + 2] = tf32r(kv.z); Ks[row][col + 3] = tf32r(kv.w);
            Vs[row][col + 0] = tf32r(vv.x); Vs[row][col + 1] = tf32r(vv.y);
            Vs[row][col + 2] = tf32r(vv.z); Vs[row][col + 3] = tf32r(vv.w);
        }
        __syncthreads();

        if (k0 > q0 + r0 + 15) continue;

        float accS[8][4];
#pragma unroll
        for (int nf = 0; nf < 8; nf++)
#pragma unroll
            for (int r = 0; r < 4; r++) accS[nf][r] = 0.0f;

#pragma unroll
        for (int ks = 0; ks < 8; ks++) {
            const int kb = ks * 8;
            uint32_t a0 = __float_as_uint(Qs[r0 + gId][kb + tig]);
            uint32_t a1 = __float_as_uint(Qs[r0 + gId + 8][kb + tig]);
            uint32_t a2 = __float_as_uint(Qs[r0 + gId][kb + tig + 4]);
            uint32_t a3 = __float_as_uint(Qs[r0 + gId + 8][kb + tig + 4]);
#pragma unroll
            for (int nf = 0; nf < 8; nf++) {
                uint32_t b0 = __float_as_uint(Ks[nf * 8 + gId][kb + tig]);
                uint32_t b1 = __float_as_uint(Ks[nf * 8 + gId][kb + tig + 4]);
                MMA_TF32(accS[nf], a0, a1, a2, a3, b0, b1);
            }
        }

        if (k0 + 63 > q0 + r0) {
            const int rlo = q0 + r0 + gId, rhi = rlo + 8;
#pragma unroll
            for (int nf = 0; nf < 8; nf++) {
                int cg = k0 + nf * 8 + 2 * tig;
                if (cg > rlo)     accS[nf][0] = -1e30f;
                if (cg + 1 > rlo) accS[nf][1] = -1e30f;
                if (cg > rhi)     accS[nf][2] = -1e30f;
                if (cg + 1 > rhi) accS[nf][3] = -1e30f;
            }
        }

#pragma unroll
        for (int r = 0; r < 2; r++) {
            float vmax = -1e30f;
#pragma unroll
            for (int nf = 0; nf < 8; nf++)
                vmax = fmaxf(vmax, fmaxf(accS[nf][2 * r], accS[nf][2 * r + 1]));
            vmax = fmaxf(vmax, __shfl_xor_sync(0xffffffffu, vmax, 1));
            vmax = fmaxf(vmax, __shfl_xor_sync(0xffffffffu, vmax, 2));
            float mnew = fmaxf(mrow[r], vmax);
            float sum = 0.0f;
#pragma unroll
            for (int nf = 0; nf < 8; nf++) {
                accS[nf][2 * r]     = __expf(accS[nf][2 * r] - mnew);
                accS[nf][2 * r + 1] = __expf(accS[nf][2 * r + 1] - mnew);
                sum += accS[nf][2 * r] + accS[nf][2 * r + 1];
            }
            sum += __shfl_xor_sync(0xffffffffu, sum, 1);
            sum += __shfl_xor_sync(0xffffffffu, sum, 2);
            float alpha = __expf(mrow[r] - mnew);
            lrow[r] = lrow[r] * alpha + sum;
            mrow[r] = mnew;
#pragma unroll
            for (int nf = 0; nf < 8; nf++) {
                accO[nf][2 * r]     *= alpha;
                accO[nf][2 * r + 1] *= alpha;
            }
        }

        __syncwarp();
#pragma unroll
        for (int nf = 0; nf < 8; nf++) {
            *(float2*)&Ps[r0 + gId][nf * 8 + 2 * tig] =
                make_float2(accS[nf][0], accS[nf][1]);
            *(float2*)&Ps[r0 + gId + 8][nf * 8 + 2 * tig] =
                make_float2(accS[nf][2], accS[nf][3]);
        }
        __syncwarp();

#pragma unroll
        for (int ks = 0; ks < 8; ks++) {
            const int kb = ks * 8;
            uint32_t a0 = __float_as_uint(Ps[r0 + gId][kb + tig]);
            uint32_t a1 = __float_as_uint(Ps[r0 + gId + 8][kb + tig]);
            uint32_t a2 = __float_as_uint(Ps[r0 + gId][kb + tig + 4]);
            uint32_t a3 = __float_as_uint(Ps[r0 + gId + 8][kb + tig + 4]);
#pragma unroll
            for (int nf = 0; nf < 8; nf++) {
                uint32_t b0 = __float_as_uint(Vs[kb + tig][nf * 8 + gId]);
                uint32_t b1 = __float_as_uint(Vs[kb + tig + 4][nf * 8 + gId]);
                MMA_TF32(accO[nf], a0, a1, a2, a3, b0, b1);
            }
        }
    }

    // epilogue: normalize, tf32-round (proj GEMM input), write y
    const float inv0 = 1.0f / lrow[0];
    const float inv1 = 1.0f / lrow[1];
    const size_t rlo = (size_t)(b * SEQ + q0 + r0 + gId);
#pragma unroll
    for (int nf = 0; nf < 8; nf++) {
        int col = h * HD + nf * 8 + 2 * tig;
        *(float2*)&g_y[rlo * D_MODEL + col] =
            make_float2(tf32r(accO[nf][0] * inv0), tf32r(accO[nf][1] * inv0));
        *(float2*)&g_y[(rlo + 8) * D_MODEL + col] =
            make_float2(tf32r(accO[nf][2] * inv1), tf32r(accO[nf][3] * inv1));
    }
}

// ---------------------------------------------------------------------------
extern "C" void kernel_launch(void* const* d_in, const int* in_sizes, int n_in,
                              void* d_out, int out_size)
{
    const float* x      = (const float*)d_in[0];   // [4,2048,1024]
    const float* w_qkv  = (const float*)d_in[1];   // [1024,3072]
    const float* w_proj = (const float*)d_in[2];   // [1024,1024]
    float* out = (float*)d_out;                    // [4,2048,1024]

    float *qkv_ptr, *y_ptr, *xr_ptr, *wqkvr_ptr, *wprojr_ptr;
    cudaGetSymbolAddress((void**)&qkv_ptr, g_qkv);
    cudaGetSymbolAddress((void**)&y_ptr, g_y);
    cudaGetSymbolAddress((void**)&xr_ptr, g_xr);
    cudaGetSymbolAddress((void**)&wqkvr_ptr, g_wqkvr);
    cudaGetSymbolAddress((void**)&wprojr_ptr, g_wprojr);

    cudaFuncSetAttribute(gemm_tf32_v2,
                         cudaFuncAttributeMaxDynamicSharedMemorySize, GEMM_SMEM);
    cudaFuncSetAttribute(flash_attn_mma,
                         cudaFuncAttributeMaxDynamicSharedMemorySize, FA_SMEM);

    // 0) tf32-round inputs (prepass)
    {
        int n4;
        n4 = MTOK * D_MODEL / 4;
        round_tf32_kernel<<<(n4 + 255) / 256, 256>>>(x, xr_ptr, n4);
        n4 = D_MODEL * 3 * D_MODEL / 4;
        round_tf32_kernel<<<(n4 + 255) / 256, 256>>>(w_qkv, wqkvr_ptr, n4);
        n4 = D_MODEL * D_MODEL / 4;
        round_tf32_kernel<<<(n4 + 255) / 256, 256>>>(w_proj, wprojr_ptr, n4);
    }

    // 1) qkv = x @ w_qkv   (tf32 mma, cp.async 3-stage, 2 CTAs/SM)
    gemm_tf32_v2<<<dim3(3 * D_MODEL / 128, MTOK / 128), 256, GEMM_SMEM>>>(
        xr_ptr, wqkvr_ptr, qkv_ptr, MTOK, 3 * D_MODEL, D_MODEL);

    // 2) flash attention (tf32 mma) -> g_y (rounded)
    flash_attn_mma<<<dim3(SEQ / 128, NHEADS, BATCH), 256, FA_SMEM>>>();

    // 3) out = y @ w_proj  (tf32 mma, cp.async 3-stage, 2 CTAs/SM)
    gemm_tf32_v2<<<dim3(D_MODEL / 128, MTOK / 128), 256, GEMM_SMEM>>>(
        y_ptr, wprojr_ptr, out, MTOK, D_MODEL, D_MODEL);
}

// round 10
// speedup vs baseline: 3.3132x; 1.0519x over previous
#include <cuda_runtime.h>
#include <math.h>
#include <stdint.h>

// Problem constants
#define D_MODEL 1024
#define NHEADS  16
#define HD      64
#define BATCH   4
#define SEQ     2048
#define MTOK    (BATCH * SEQ)   // 8192 rows

// Scratch (device globals: allocation inside kernel_launch is forbidden)
__device__ float g_qkv[(size_t)MTOK * 3 * D_MODEL];     // [8192, 3072] (tf32-rounded)
__device__ float g_y  [(size_t)MTOK * D_MODEL];         // [8192, 1024] (tf32-rounded)
__device__ float g_xr [(size_t)MTOK * D_MODEL];         // tf32-rounded x
__device__ float g_wqkvr[(size_t)D_MODEL * 3 * D_MODEL];// tf32-rounded w_qkv
__device__ float g_wprojr[(size_t)D_MODEL * D_MODEL];   // tf32-rounded w_proj

// ---------------------------------------------------------------------------
__device__ __forceinline__ float tf32r(float x) {
    uint32_t o;
    asm("cvt.rna.tf32.f32 %0, %1;" : "=r"(o) : "f"(x));
    return __uint_as_float(o);
}

#define MMA_TF32(acc, a0, a1, a2, a3, b0, b1) \
    asm volatile( \
        "mma.sync.aligned.m16n8k8.row.col.f32.tf32.tf32.f32 " \
        "{%0,%1,%2,%3}, {%4,%5,%6,%7}, {%8,%9}, {%0,%1,%2,%3};" \
        : "+f"((acc)[0]), "+f"((acc)[1]), "+f"((acc)[2]), "+f"((acc)[3]) \
        : "r"(a0), "r"(a1), "r"(a2), "r"(a3), "r"(b0), "r"(b1))

__device__ __forceinline__ uint32_t smem_u32(const void* p) {
    uint32_t a;
    asm("{ .reg .u64 t; cvta.to.shared.u64 t, %1; cvt.u32.u64 %0, t; }" : "=r"(a) : "l"(p));
    return a;
}
__device__ __forceinline__ void cp_async16(uint32_t dst, const void* src) {
    asm volatile("cp.async.cg.shared.global [%0], [%1], 16;" :: "r"(dst), "l"(src));
}
#define CP_COMMIT() asm volatile("cp.async.commit_group;" ::: "memory")
#define CP_WAIT_GROUP(n) asm volatile("cp.async.wait_group %0;" :: "n"(n) : "memory")

// ---------------------------------------------------------------------------
// tf32 rounding prepass (vectorized)
// ---------------------------------------------------------------------------
__global__ void round_tf32_kernel(const float* __restrict__ in, float* __restrict__ out, int n4)
{
    int i = blockIdx.x * blockDim.x + threadIdx.x;
    if (i < n4) {
        float4 v = ((const float4*)in)[i];
        ((float4*)out)[i] = make_float4(tf32r(v.x), tf32r(v.y), tf32r(v.z), tf32r(v.w));
    }
}

// ---------------------------------------------------------------------------
// TF32 mma.sync GEMM: C[M,N] = A[M,K] @ B[K,N], row-major, pre-rounded inputs.
// 128x128 CTA tile, BK=32, 3-stage cp.async, 8 warps (2x4), warp tile 64x32,
// 2 CTAs/SM. round_out: tf32-round C (used for qkv so flash can cp.async it).
// ---------------------------------------------------------------------------
#define GBK 32
#define GSTAGES 3
#define A_STR 36
#define B_STR 136
#define STAGE_FLOATS (128 * A_STR + GBK * B_STR)   // 8960
#define GEMM_SMEM (GSTAGES * STAGE_FLOATS * 4)     // 107520 B

__global__ __launch_bounds__(256, 2)
void gemm_tf32_v2(const float* __restrict__ A, const float* __restrict__ B,
                  float* __restrict__ C, int M, int N, int K, int round_out)
{
    extern __shared__ float sm[];
    const uint32_t sbase = smem_u32(sm);

    const int tid = threadIdx.x;
    const int wid = tid >> 5, lane = tid & 31;
    const int wm = wid >> 2, wn = wid & 3;
    const int gId = lane >> 2, tig = lane & 3;
    const int bm = blockIdx.y, bn = blockIdx.x;

    const float* Ab = A + (size_t)(bm * 128) * K;
    const float* Bb = B + bn * 128;

    float acc[4][4][4];
#pragma unroll
    for (int i = 0; i < 4; i++)
#pragma unroll
        for (int j = 0; j < 4; j++)
#pragma unroll
            for (int r = 0; r < 4; r++) acc[i][j][r] = 0.0f;

    auto load_stage = [&](int kt, int s) {
        const uint32_t aT = sbase + (uint32_t)(s * STAGE_FLOATS) * 4;
        const uint32_t bT = aT + 128 * A_STR * 4;
        const int k0 = kt * GBK;
#pragma unroll
        for (int i = 0; i < 4; i++) {
            int c = tid + 256 * i;
            int row = c >> 3, kc = (c & 7) * 4;
            cp_async16(aT + (uint32_t)(row * A_STR + kc) * 4,
                       Ab + (size_t)row * K + k0 + kc);
        }
#pragma unroll
        for (int i = 0; i < 4; i++) {
            int c = tid + 256 * i;
            int row = c >> 5, nc = (c & 31) * 4;
            cp_async16(bT + (uint32_t)(row * B_STR + nc) * 4,
                       Bb + (size_t)(k0 + row) * N + nc);
        }
    };

    auto compute = [&](int s) {
        const float* As = sm + s * STAGE_FLOATS;
        const float* Bs = As + 128 * A_STR;
#pragma unroll
        for (int ks = 0; ks < 4; ks++) {
            const int kb = ks * 8;
            uint32_t a[4][4], b[4][2];
#pragma unroll
            for (int mf = 0; mf < 4; mf++) {
                int m0 = wm * 64 + mf * 16 + gId;
                a[mf][0] = __float_as_uint(As[m0 * A_STR + kb + tig]);
                a[mf][1] = __float_as_uint(As[(m0 + 8) * A_STR + kb + tig]);
                a[mf][2] = __float_as_uint(As[m0 * A_STR + kb + tig + 4]);
                a[mf][3] = __float_as_uint(As[(m0 + 8) * A_STR + kb + tig + 4]);
            }
#pragma unroll
            for (int nf = 0; nf < 4; nf++) {
                int n0 = wn * 32 + nf * 8 + gId;
                b[nf][0] = __float_as_uint(Bs[(kb + tig) * B_STR + n0]);
                b[nf][1] = __float_as_uint(Bs[(kb + tig + 4) * B_STR + n0]);
            }
#pragma unroll
            for (int mf = 0; mf < 4; mf++)
#pragma unroll
                for (int nf = 0; nf < 4; nf++)
                    MMA_TF32(acc[mf][nf], a[mf][0], a[mf][1], a[mf][2], a[mf][3],
                             b[nf][0], b[nf][1]);
        }
    };

    const int nkt = K / GBK;
    load_stage(0, 0); CP_COMMIT();
    load_stage(1, 1); CP_COMMIT();

    for (int kt = 0; kt < nkt; kt++) {
        CP_WAIT_GROUP(1);
        __syncthreads();
        if (kt + 2 < nkt) load_stage(kt + 2, (kt + 2) % GSTAGES);
        CP_COMMIT();
        compute(kt % GSTAGES);
    }

#pragma unroll
    for (int mf = 0; mf < 4; mf++) {
        int r0 = bm * 128 + wm * 64 + mf * 16 + gId;
#pragma unroll
        for (int nf = 0; nf < 4; nf++) {
            int c0 = bn * 128 + wn * 32 + nf * 8 + 2 * tig;
            float2 v0 = make_float2(acc[mf][nf][0], acc[mf][nf][1]);
            float2 v1 = make_float2(acc[mf][nf][2], acc[mf][nf][3]);
            if (round_out) {
                v0.x = tf32r(v0.x); v0.y = tf32r(v0.y);
                v1.x = tf32r(v1.x); v1.y = tf32r(v1.y);
            }
            *(float2*)&C[(size_t)r0 * N + c0] = v0;
            *(float2*)&C[(size_t)(r0 + 8) * N + c0] = v1;
        }
    }
}

// ---------------------------------------------------------------------------
// Flash attention v2: tf32 mma, causal, online softmax.
// - qkv is pre-rounded (GEMM epilogue) -> Q/K/V via cp.async, no converts.
// - K/V double-buffered, depth-2 pipeline: prefetch jt+1 during compute jt.
// - Q unscaled in smem; S *= 0.125 post-mma (exact, exponent shift).
// - P redistributed C-frag -> A-frag via quad shfl (no Ps smem buffer).
// Smem: Qs 128x68 + 2x(K 64x68) + 2x(V 64x72) = 106496 B -> 2 CTAs/SM.
// ---------------------------------------------------------------------------
#define QSTR 68
#define KSTR 68
#define VSTR 72
#define FA_SMEM ((128 * QSTR + 2 * 64 * KSTR + 2 * 64 * VSTR) * 4)  // 106496

__global__ __launch_bounds__(256, 2)
void flash_attn_mma()
{
    extern __shared__ float smf[];
    float (*Qs)[QSTR] = (float(*)[QSTR])smf;
    float* Kbase = smf + 128 * QSTR;
    float* Vbase = Kbase + 2 * 64 * KSTR;

    const int tid = threadIdx.x;
    const int wid = tid >> 5, lane = tid & 31;
    const int gId = lane >> 2, tig = lane & 3;
    const int b = blockIdx.z, h = blockIdx.y;
    const int qt = gridDim.x - 1 - blockIdx.x;   // heavy blocks first
    const int q0 = qt * 128;
    const int r0 = wid * 16;

    const uint32_t sb = smem_u32(smf);
    const uint32_t qb_u = sb;
    const uint32_t kb_u = sb + 128 * QSTR * 4;
    const uint32_t vb_u = kb_u + 2 * 64 * KSTR * 4;

    // K/V tile loader: 64x64 floats each, 4 chunks/thread each
    auto load_kv = [&](int jt, int s) {
        const int k0 = jt * 64;
        const uint32_t kT = kb_u + (uint32_t)(s * 64 * KSTR) * 4;
        const uint32_t vT = vb_u + (uint32_t)(s * 64 * VSTR) * 4;
#pragma unroll
        for (int i = 0; i < 4; i++) {
            int idx = tid + 256 * i;
            int row = idx >> 4, col = (idx & 15) * 4;
            const float* kp = g_qkv + (size_t)(b * SEQ + k0 + row) * (3 * D_MODEL)
                              + D_MODEL + h * HD + col;
            cp_async16(kT + (uint32_t)(row * KSTR + col) * 4, kp);
            cp_async16(vT + (uint32_t)(row * VSTR + col) * 4, kp + D_MODEL);
        }
    };

    // prologue: Q (8 chunks/thread) + K/V tile 0, one group
#pragma unroll
    for (int i = 0; i < 8; i++) {
        int idx = tid + 256 * i;
        int row = idx >> 4, col = (idx & 15) * 4;
        cp_async16(qb_u + (uint32_t)(row * QSTR + col) * 4,
                   g_qkv + (size_t)(b * SEQ + q0 + row) * (3 * D_MODEL) + h * HD + col);
    }
    load_kv(0, 0);
    CP_COMMIT();

    float accO[8][4];
#pragma unroll
    for (int nf = 0; nf < 8; nf++)
#pragma unroll
        for (int r = 0; r < 4; r++) accO[nf][r] = 0.0f;
    float mrow[2] = {-1e30f, -1e30f};
    float lrow[2] = {0.0f, 0.0f};

    const int ktiles = 2 * qt + 2;
    for (int jt = 0; jt < ktiles; jt++) {
        const int s = jt & 1;
        const int k0 = jt * 64;
        CP_WAIT_GROUP(0);        // tile jt (and Q on jt=0) resident for this thread
        __syncthreads();         // cross-thread visibility + stage s^1 reads done
        if (jt + 1 < ktiles) { load_kv(jt + 1, s ^ 1); CP_COMMIT(); }

        if (k0 > q0 + r0 + 15) continue;   // warp fully below this key tile

        const float* Ks = Kbase + s * 64 * KSTR;
        const float* Vs = Vbase + s * 64 * VSTR;

        // ---- S = Q @ K^T ----
        float accS[8][4];
#pragma unroll
        for (int nf = 0; nf < 8; nf++)
#pragma unroll
            for (int r = 0; r < 4; r++) accS[nf][r] = 0.0f;

#pragma unroll
        for (int ks = 0; ks < 8; ks++) {
            const int kb = ks * 8;
            uint32_t a0 = __float_as_uint(Qs[r0 + gId][kb + tig]);
            uint32_t a1 = __float_as_uint(Qs[r0 + gId + 8][kb + tig]);
            uint32_t a2 = __float_as_uint(Qs[r0 + gId][kb + tig + 4]);
            uint32_t a3 = __float_as_uint(Qs[r0 + gId + 8][kb + tig + 4]);
#pragma unroll
            for (int nf = 0; nf < 8; nf++) {
                uint32_t b0 = __float_as_uint(Ks[(nf * 8 + gId) * KSTR + kb + tig]);
                uint32_t b1 = __float_as_uint(Ks[(nf * 8 + gId) * KSTR + kb + tig + 4]);
                MMA_TF32(accS[nf], a0, a1, a2, a3, b0, b1);
            }
        }

        // ---- scale (1/sqrt(64), exact exponent shift) ----
#pragma unroll
        for (int nf = 0; nf < 8; nf++)
#pragma unroll
            for (int r = 0; r < 4; r++) accS[nf][r] *= 0.125f;

        // ---- causal mask (near-diagonal tiles only) ----
        if (k0 + 63 > q0 + r0) {
            const int rlo = q0 + r0 + gId, rhi = rlo + 8;
#pragma unroll
            for (int nf = 0; nf < 8; nf++) {
                int cg = k0 + nf * 8 + 2 * tig;
                if (cg > rlo)     accS[nf][0] = -1e30f;
                if (cg + 1 > rlo) accS[nf][1] = -1e30f;
                if (cg > rhi)     accS[nf][2] = -1e30f;
                if (cg + 1 > rhi) accS[nf][3] = -1e30f;
            }
        }

        // ---- online softmax (rows gId, gId+8; quad-lane reduction) ----
#pragma unroll
        for (int r = 0; r < 2; r++) {
            float vmax = -1e30f;
#pragma unroll
            for (int nf = 0; nf < 8; nf++)
                vmax = fmaxf(vmax, fmaxf(accS[nf][2 * r], accS[nf][2 * r + 1]));
            vmax = fmaxf(vmax, __shfl_xor_sync(0xffffffffu, vmax, 1));
            vmax = fmaxf(vmax, __shfl_xor_sync(0xffffffffu, vmax, 2));
            float mnew = fmaxf(mrow[r], vmax);
            float sum = 0.0f;
#pragma unroll
            for (int nf = 0; nf < 8; nf++) {
                accS[nf][2 * r]     = __expf(accS[nf][2 * r] - mnew);
                accS[nf][2 * r + 1] = __expf(accS[nf][2 * r + 1] - mnew);
                sum += accS[nf][2 * r] + accS[nf][2 * r + 1];
            }
            sum += __shfl_xor_sync(0xffffffffu, sum, 1);
            sum += __shfl_xor_sync(0xffffffffu, sum, 2);
            float alpha = __expf(mrow[r] - mnew);
            lrow[r] = lrow[r] * alpha + sum;
            mrow[r] = mnew;
#pragma unroll
            for (int nf = 0; nf < 8; nf++) {
                accO[nf][2 * r]     *= alpha;
                accO[nf][2 * r + 1] *= alpha;
            }
        }

        // ---- O += P @ V, P A-frags built from accS C-frags via quad shfl ----
        // col c (in 8-group) lives in lane gId*4 + (c>>1), element c&1.
#pragma unroll
        for (int ks = 0; ks < 8; ks++) {
            const int kb = ks * 8;
            const int s0 = (lane & ~3) | (tig >> 1);   // src for col tig
            const int s1 = s0 + 2;                     // src for col tig+4
            float e00 = __shfl_sync(0xffffffffu, accS[ks][0], s0);
            float e01 = __shfl_sync(0xffffffffu, accS[ks][1], s0);
            float e10 = __shfl_sync(0xffffffffu, accS[ks][2], s0);
            float e11 = __shfl_sync(0xffffffffu, accS[ks][3], s0);
            float f00 = __shfl_sync(0xffffffffu, accS[ks][0], s1);
            float f01 = __shfl_sync(0xffffffffu, accS[ks][1], s1);
            float f10 = __shfl_sync(0xffffffffu, accS[ks][2], s1);
            float f11 = __shfl_sync(0xffffffffu, accS[ks][3], s1);
            const bool odd = (tig & 1);
            uint32_t a0 = __float_as_uint(odd ? e01 : e00);
            uint32_t a1 = __float_as_uint(odd ? e11 : e10);
            uint32_t a2 = __float_as_uint(odd ? f01 : f00);
            uint32_t a3 = __float_as_uint(odd ? f11 : f10);
#pragma unroll
            for (int nf = 0; nf < 8; nf++) {
                uint32_t b0 = __float_as_uint(Vs[(kb + tig) * VSTR + nf * 8 + gId]);
                uint32_t b1 = __float_as_uint(Vs[(kb + tig + 4) * VSTR + nf * 8 + gId]);
                MMA_TF32(accO[nf], a0, a1, a2, a3, b0, b1);
            }
        }
    }

    // epilogue: normalize, tf32-round (proj GEMM input), write y
    const float inv0 = 1.0f / lrow[0];
    const float inv1 = 1.0f / lrow[1];
    const size_t rlo = (size_t)(b * SEQ + q0 + r0 + gId);
#pragma unroll
    for (int nf = 0; nf < 8; nf++) {
        int col = h * HD + nf * 8 + 2 * tig;
        *(float2*)&g_y[rlo * D_MODEL + col] =
            make_float2(tf32r(accO[nf][0] * inv0), tf32r(accO[nf][1] * inv0));
        *(float2*)&g_y[(rlo + 8) * D_MODEL + col] =
            make_float2(tf32r(accO[nf][2] * inv1), tf32r(accO[nf][3] * inv1));
    }
}

// ---------------------------------------------------------------------------
extern "C" void kernel_launch(void* const* d_in, const int* in_sizes, int n_in,
                              void* d_out, int out_size)
{
    const float* x      = (const float*)d_in[0];   // [4,2048,1024]
    const float* w_qkv  = (const float*)d_in[1];   // [1024,3072]
    const float* w_proj = (const float*)d_in[2];   // [1024,1024]
    float* out = (float*)d_out;                    // [4,2048,1024]

    float *qkv_ptr, *y_ptr, *xr_ptr, *wqkvr_ptr, *wprojr_ptr;
    cudaGetSymbolAddress((void**)&qkv_ptr, g_qkv);
    cudaGetSymbolAddress((void**)&y_ptr, g_y);
    cudaGetSymbolAddress((void**)&xr_ptr, g_xr);
    cudaGetSymbolAddress((void**)&wqkvr_ptr, g_wqkvr);
    cudaGetSymbolAddress((void**)&wprojr_ptr, g_wprojr);

    cudaFuncSetAttribute(gemm_tf32_v2,
                         cudaFuncAttributeMaxDynamicSharedMemorySize, GEMM_SMEM);
    cudaFuncSetAttribute(flash_attn_mma,
                         cudaFuncAttributeMaxDynamicSharedMemorySize, FA_SMEM);

    // 0) tf32-round inputs (prepass)
    {
        int n4;
        n4 = MTOK * D_MODEL / 4;
        round_tf32_kernel<<<(n4 + 255) / 256, 256>>>(x, xr_ptr, n4);
        n4 = D_MODEL * 3 * D_MODEL / 4;
        round_tf32_kernel<<<(n4 + 255) / 256, 256>>>(w_qkv, wqkvr_ptr, n4);
        n4 = D_MODEL * D_MODEL / 4;
        round_tf32_kernel<<<(n4 + 255) / 256, 256>>>(w_proj, wprojr_ptr, n4);
    }

    // 1) qkv = x @ w_qkv   (rounded output -> flash cp.async path)
    gemm_tf32_v2<<<dim3(3 * D_MODEL / 128, MTOK / 128), 256, GEMM_SMEM>>>(
        xr_ptr, wqkvr_ptr, qkv_ptr, MTOK, 3 * D_MODEL, D_MODEL, 1);

    // 2) flash attention v2 (pipelined) -> g_y (rounded)
    flash_attn_mma<<<dim3(SEQ / 128, NHEADS, BATCH), 256, FA_SMEM>>>();

    // 3) out = y @ w_proj  (fp32 output)
    gemm_tf32_v2<<<dim3(D_MODEL / 128, MTOK / 128), 256, GEMM_SMEM>>>(
        y_ptr, wprojr_ptr, out, MTOK, D_MODEL, D_MODEL, 0);
}